// round 7
// baseline (speedup 1.0000x reference)
#include <cuda_runtime.h>
#include <cuda_bf16.h>
#include <mma.h>
#include <math.h>
#include <stdint.h>

using namespace nvcuda;
typedef __nv_bfloat16 bf16;

#define EPS 1e-5f

#define BATCH 4
#define HH 64
#define WW 64
#define HW 4096
#define CC 512
#define KK 19
#define PP 64
#define NN 64
#define DD 256
#define CIN3 2560

// ---------------- scratch ----------------
__device__ float g_Fnhwc[BATCH * HW * CC];
__device__ float g_Fl[BATCH * PP * KK * CC];
__device__ float g_Fl2[BATCH * PP * KK * CC];
__device__ float g_Fg[BATCH * KK * CC];
__device__ float g_query[BATCH * HW * DD];
__device__ float g_key[BATCH * PP * KK * DD];
__device__ float g_value[BATCH * KK * DD];
__device__ float g_x3[BATCH * HW * CC];

// bf16 hi/lo pairs (activations)
__device__ bf16 g_Fh[BATCH * HW * CC];
__device__ bf16 g_Flo[BATCH * HW * CC];
__device__ bf16 g_hh[BATCH * PP * KK * CC];
__device__ bf16 g_hl[BATCH * PP * KK * CC];
__device__ bf16 g_Fl2h[BATCH * PP * KK * CC];
__device__ bf16 g_Fl2l[BATCH * PP * KK * CC];
__device__ bf16 g_Fsh[BATCH * HW * DD];
__device__ bf16 g_Fsl[BATCH * HW * DD];
__device__ bf16 g_cath[(size_t)BATCH * HW * CIN3];
__device__ bf16 g_catl[(size_t)BATCH * HW * CIN3];
__device__ bf16 g_Fo1h[BATCH * HW * CC];
__device__ bf16 g_Fo1l[BATCH * HW * CC];

// bf16 hi/lo pairs (weights)
__device__ bf16 g_w2h[512 * 512 * 9];
__device__ bf16 g_w2l[512 * 512 * 9];
__device__ bf16 g_w3h[512 * 2560 * 9];
__device__ bf16 g_w3l[512 * 2560 * 9];
__device__ bf16 g_qwh[512 * 256], g_qwl[512 * 256];     // [K=512][N=256]
__device__ bf16 g_kwh[512 * 256], g_kwl[512 * 256];
__device__ bf16 g_lgwh[512 * 512], g_lgwl[512 * 512];   // [K=512][N=512]
__device__ bf16 g_c1h[256 * 512], g_c1l[256 * 512];     // [K=256][N=512]

__device__ __forceinline__ void split_bf16(float v, bf16& hi, bf16& lo) {
    hi = __float2bfloat16(v);
    lo = __float2bfloat16(v - __bfloat162float(hi));
}

// cp.async helpers
__device__ __forceinline__ void cpa16(void* sdst, const void* gsrc, bool pred) {
    unsigned int s = (unsigned int)__cvta_generic_to_shared(sdst);
    int sz = pred ? 16 : 0;
    asm volatile("cp.async.cg.shared.global [%0], [%1], 16, %2;" :: "r"(s), "l"(gsrc), "r"(sz));
}
__device__ __forceinline__ void cpa_commit() {
    asm volatile("cp.async.commit_group;");
}
template <int N>
__device__ __forceinline__ void cpa_wait() {
    asm volatile("cp.async.wait_group %0;" :: "n"(N));
}

// ---------------- transpose NCHW -> NHWC: fp32 + bf16 pair ----------------
__global__ void k_transpose_f(const float* __restrict__ in, float* __restrict__ out,
                              bf16* __restrict__ oh, bf16* __restrict__ ol) {
    __shared__ float tile[32][33];
    int b = blockIdx.z;
    int hw0 = blockIdx.x * 32, c0 = blockIdx.y * 32;
    int tx = threadIdx.x, ty = threadIdx.y;
    for (int i = ty; i < 32; i += 8)
        tile[i][tx] = in[((size_t)b * CC + c0 + i) * HW + hw0 + tx];
    __syncthreads();
    for (int i = ty; i < 32; i += 8) {
        float v = tile[tx][i];
        size_t o = ((size_t)b * HW + hw0 + i) * CC + c0 + tx;
        out[o] = v;
        bf16 hi, lo; split_bf16(v, hi, lo);
        oh[o] = hi; ol[o] = lo;
    }
}

// ---------------- transpose NCHW -> NHWC (bf16 hi/lo only) ----------------
__global__ void k_transpose_pair(const float* __restrict__ in, bf16* __restrict__ oh,
                                 bf16* __restrict__ ol, int C, int out_stride, int col_off) {
    __shared__ float tile[32][33];
    int b = blockIdx.z;
    int hw0 = blockIdx.x * 32, c0 = blockIdx.y * 32;
    int tx = threadIdx.x, ty = threadIdx.y;
    for (int i = ty; i < 32; i += 8)
        tile[i][tx] = in[((size_t)b * C + c0 + i) * HW + hw0 + tx];
    __syncthreads();
    for (int i = ty; i < 32; i += 8) {
        float v = tile[tx][i];
        bf16 hi, lo; split_bf16(v, hi, lo);
        size_t o = ((size_t)b * HW + hw0 + i) * out_stride + col_off + c0 + tx;
        oh[o] = hi; ol[o] = lo;
    }
}

// ---------------- conv weight split, dst-ordered: OIHW -> [(ky*3+kx)][Cin][OutC] ----------------
__global__ void k_wsplit(const float* __restrict__ w, bf16* __restrict__ oh,
                         bf16* __restrict__ ol, int OutC, int Cin) {
    size_t d = (size_t)blockIdx.x * 256 + threadIdx.x;
    size_t total = (size_t)OutC * Cin * 9;
    if (d >= total) return;
    int o = d % OutC;
    size_t t2 = d / OutC;
    int i = t2 % Cin;
    int kq = t2 / Cin;
    float v = w[((size_t)o * Cin + i) * 9 + kq];
    bf16 hi, lo; split_bf16(v, hi, lo);
    oh[d] = hi; ol[d] = lo;
}

// ---------------- GEMM weight transpose+split: w[N,K] -> wt[K][N] pair ----------------
__global__ void k_wtsplit(const float* __restrict__ w, bf16* __restrict__ oh,
                          bf16* __restrict__ ol, int K, int N) {
    int d = blockIdx.x * 256 + threadIdx.x;
    if (d >= K * N) return;
    int k = d / N, n = d % N;
    float v = w[(size_t)n * K + k];
    bf16 hi, lo; split_bf16(v, hi, lo);
    oh[d] = hi; ol[d] = lo;
}

// ---------------- patch softmax + F_l ----------------
__global__ void k_patch_fl(const float* __restrict__ I, const float* __restrict__ R) {
    int bp = blockIdx.x;
    int b = bp >> 6, p = bp & 63;
    int ph = p >> 3, pw = p & 7;
    int tid = threadIdx.x;

    __shared__ float lg[KK][NN];
    __shared__ float pix[NN][20];
    __shared__ float bc[KK];
    __shared__ float Fp[NN][65];

    for (int idx = tid; idx < KK * NN; idx += 256) {
        int k = idx / NN, n = idx % NN;
        int h = ph * 8 + (n >> 3), w = pw * 8 + (n & 7);
        lg[k][n] = I[(((size_t)b * KK + k) * HH + h) * WW + w];
    }
    if (tid < KK) bc[tid] = R[((size_t)b * KK + tid) * PP + p];
    __syncthreads();

    if (tid < KK) {
        float mx = -1e30f;
        for (int n = 0; n < NN; n++) mx = fmaxf(mx, lg[tid][n]);
        float s = 0.f;
        for (int n = 0; n < NN; n++) { float e = __expf(lg[tid][n] - mx); pix[n][tid] = e; s += e; }
        float inv = 1.f / s;
        for (int n = 0; n < NN; n++) pix[n][tid] *= inv;
    }
    __syncthreads();

    for (int c0 = 0; c0 < CC; c0 += 64) {
        for (int idx = tid; idx < NN * 64; idx += 256) {
            int n = idx >> 6, cc = idx & 63;
            int h = ph * 8 + (n >> 3), w = pw * 8 + (n & 7);
            Fp[n][cc] = g_Fnhwc[((size_t)b * HW + h * WW + w) * CC + c0 + cc];
        }
        __syncthreads();
        for (int o = tid; o < KK * 64; o += 256) {
            int k = o >> 6, cc = o & 63;
            float acc = 0.f;
            #pragma unroll 8
            for (int n = 0; n < NN; n++) acc += pix[n][k] * Fp[n][cc];
            g_Fl[((size_t)bp * KK + k) * CC + c0 + cc] = acc * bc[k];
        }
        __syncthreads();
    }
}

// ---------------- h = relu(lg_w1 @p F_l + F_l) -> bf16 pair ----------------
__global__ void k_lg1(const float* __restrict__ lg_w1) {
    int c0 = blockIdx.x * 64;
    int bk = blockIdx.y;
    int b = bk / KK, k = bk % KK;
    int tid = threadIdx.x;
    __shared__ float w1[64][64];
    __shared__ float Fl[64][65];
    for (int idx = tid; idx < 4096; idx += 256) w1[idx >> 6][idx & 63] = lg_w1[idx];
    for (int idx = tid; idx < 4096; idx += 256) {
        int p = idx >> 6, cc = idx & 63;
        Fl[p][cc] = g_Fl[(((size_t)b * PP + p) * KK + k) * CC + c0 + cc];
    }
    __syncthreads();
    for (int o = tid; o < 4096; o += 256) {
        int q = o >> 6, cc = o & 63;
        float acc = Fl[q][cc];
        #pragma unroll 8
        for (int p = 0; p < 64; p++) acc += w1[q][p] * Fl[p][cc];
        float v = fmaxf(acc, 0.f);
        bf16 hi, lo; split_bf16(v, hi, lo);
        size_t oidx = (((size_t)b * PP + q) * KK + k) * CC + c0 + cc;
        g_hh[oidx] = hi; g_hl[oidx] = lo;
    }
}

// ---------------- legacy fp32 SIMT GEMM (only for tiny value GEMM) ----------------
__global__ void k_gemm_v(const float* __restrict__ A, const float* __restrict__ Bw,
                         float* __restrict__ C, int M, int N, int K,
                         const float* __restrict__ bias) {
    __shared__ float As[16][68];
    __shared__ float Bs[16][68];
    int m0 = blockIdx.y * 64, n0 = blockIdx.x * 64;
    int tid = threadIdx.x;
    int tx = tid & 15, ty = tid >> 4;
    float acc[4][4] = {};

    for (int k0 = 0; k0 < K; k0 += 16) {
        for (int idx = tid; idx < 64 * 16; idx += 256) {
            int i = idx >> 4, kk = idx & 15;
            int m = m0 + i;
            As[kk][i] = (m < M) ? A[(size_t)m * K + k0 + kk] : 0.f;
        }
        for (int idx = tid; idx < 64 * 16; idx += 256) {
            int j = idx >> 4, kk = idx & 15;
            Bs[kk][j] = Bw[(size_t)(n0 + j) * K + k0 + kk];
        }
        __syncthreads();
        #pragma unroll
        for (int kk = 0; kk < 16; kk++) {
            float a[4], bv[4];
            #pragma unroll
            for (int i = 0; i < 4; i++) a[i] = As[kk][ty * 4 + i];
            #pragma unroll
            for (int j = 0; j < 4; j++) bv[j] = Bs[kk][tx * 4 + j];
            #pragma unroll
            for (int i = 0; i < 4; i++)
                #pragma unroll
                for (int j = 0; j < 4; j++) acc[i][j] += a[i] * bv[j];
        }
        __syncthreads();
    }

    #pragma unroll
    for (int i = 0; i < 4; i++) {
        int m = m0 + ty * 4 + i;
        if (m >= M) continue;
        #pragma unroll
        for (int j = 0; j < 4; j++) {
            int n = n0 + tx * 4 + j;
            C[(size_t)m * N + n] = acc[i][j] + bias[n];
        }
    }
}

// ---------------- fuse ----------------
__global__ void k_fuse(const float* __restrict__ fuse_w, const float* __restrict__ fuse_b) {
    int bk = blockIdx.x;
    int c = threadIdx.x;
    int b = bk / KK, k = bk % KK;
    float acc = fuse_b[0];
    #pragma unroll 8
    for (int p = 0; p < PP; p++)
        acc += fuse_w[p] * g_Fl2[(((size_t)b * PP + p) * KK + k) * CC + c];
    g_Fg[(size_t)bk * CC + c] = acc;
}

// ---------------- attention (writes F_s bf16 pair) ----------------
__global__ void k_attn() {
    int bp = blockIdx.x;
    int b = bp >> 6, p = bp & 63;
    int ph = p >> 3, pw = p & 7;
    int tid = threadIdx.x;
    __shared__ float ks[KK][DD];
    __shared__ float vs[KK][DD];
    for (int idx = tid; idx < KK * DD; idx += 256)
        ((float*)ks)[idx] = g_key[(size_t)bp * KK * DD + idx];
    for (int idx = tid; idx < KK * DD; idx += 256)
        ((float*)vs)[idx] = g_value[(size_t)b * KK * DD + idx];
    __syncthreads();

    int warp = tid >> 5, lane = tid & 31;
    for (int n = warp; n < NN; n += 8) {
        int h = ph * 8 + (n >> 3), w = pw * 8 + (n & 7);
        const float* qrow = &g_query[((size_t)b * HW + h * WW + w) * DD];
        float qr[8];
        #pragma unroll
        for (int i = 0; i < 8; i++) qr[i] = qrow[i * 32 + lane];

        float acc[KK];
        #pragma unroll
        for (int k = 0; k < KK; k++) acc[k] = 0.f;
        #pragma unroll
        for (int i = 0; i < 8; i++) {
            float qd = qr[i];
            #pragma unroll
            for (int k = 0; k < KK; k++) acc[k] += qd * ks[k][i * 32 + lane];
        }
        #pragma unroll
        for (int k = 0; k < KK; k++) {
            #pragma unroll
            for (int off = 16; off > 0; off >>= 1)
                acc[k] += __shfl_xor_sync(0xFFFFFFFFu, acc[k], off);
        }
        float mx = -1e30f;
        #pragma unroll
        for (int k = 0; k < KK; k++) mx = fmaxf(mx, acc[k]);
        float sum = 0.f;
        #pragma unroll
        for (int k = 0; k < KK; k++) { acc[k] = __expf(acc[k] - mx); sum += acc[k]; }
        float inv = 1.f / sum;
        #pragma unroll
        for (int k = 0; k < KK; k++) acc[k] *= inv;

        size_t obase = ((size_t)b * HW + h * WW + w) * DD;
        #pragma unroll
        for (int i = 0; i < 8; i++) {
            int d = i * 32 + lane;
            float o = 0.f;
            #pragma unroll
            for (int k = 0; k < KK; k++) o += acc[k] * vs[k][d];
            bf16 hi, lo; split_bf16(o, hi, lo);
            g_Fsh[obase + d] = hi; g_Fsl[obase + d] = lo;
        }
    }
}

// ---------------- generic split-bf16 wmma GEMM: C[M,N] = A[M,K] @ Wt[K,N] ----------------
// block: M0=256 x N0=128, 512 threads (16 warps = 8 warpM x 2 warpN)
// MODE 0: fp32 C + bf16 pair   MODE 1: +bias fp32   MODE 2: resid + relu(bn) -> pair
// Stage: Ah[256*16]=8192B | Al=8192B | Wh[16*136]=4352B | Wl=4352B = 25088B
#define GSTAGE_B 25088
template <int MODE>
__global__ __launch_bounds__(512)
void k_gemm_mma(const bf16* __restrict__ Ahg, const bf16* __restrict__ Alg,
                const bf16* __restrict__ Wth, const bf16* __restrict__ Wtl,
                int K, int N,
                float* __restrict__ Cf, bf16* __restrict__ Ch, bf16* __restrict__ Cl,
                const float* __restrict__ bias,
                const float* __restrict__ bng, const float* __restrict__ bnb,
                const float* __restrict__ resid) {
    extern __shared__ char smem[];
    int n0 = blockIdx.x * 128, m0 = blockIdx.y * 256;
    int tid = threadIdx.x;
    int lane = tid & 31, warp = tid >> 5;
    int warpM = warp >> 1, warpN = warp & 1;
    int iters = K >> 4;

    wmma::fragment<wmma::accumulator, 16, 16, 16, float> acc[2][4];
    #pragma unroll
    for (int mt = 0; mt < 2; mt++)
        #pragma unroll
        for (int nj = 0; nj < 4; nj++) wmma::fill_fragment(acc[mt][nj], 0.f);

    auto issue = [&](int it) {
        int k0 = it << 4;
        char* base = smem + (it & 1) * GSTAGE_B;
        bf16* Ah = (bf16*)base;
        bf16* Al = (bf16*)(base + 8192);
        bf16* Wh = (bf16*)(base + 16384);
        bf16* Wl = (bf16*)(base + 20736);
        // A: 256 rows x 16 ch (hi 512 uint4 + lo 512)
        for (int u = tid; u < 1024; u += 512) {
            int v = (u < 512) ? u : u - 512;
            int flat = v * 8;
            int r = flat >> 4, c8 = flat & 15;
            const bf16* src = (u < 512) ? Ahg : Alg;
            const bf16* g = src + (size_t)(m0 + r) * K + k0 + c8;
            bf16* dst = ((u < 512) ? Ah : Al) + flat;
            cpa16(dst, g, true);
        }
        // W: 16 k x 128 n (hi 256 uint4 + lo 256), padded rows (136)
        if (tid < 512) {
            int u = tid;
            if (u < 512) {
                int v = (u < 256) ? u : u - 256;
                int flat = v * 8;
                int kk = flat >> 7, n8 = flat & 127;
                const bf16* src = (u < 256) ? Wth : Wtl;
                const bf16* g = src + (size_t)(k0 + kk) * N + n0 + n8;
                bf16* dst = ((u < 256) ? Wh : Wl) + kk * 136 + n8;
                cpa16(dst, g, true);
            }
        }
        cpa_commit();
    };

    issue(0);

    for (int it = 0; it < iters; it++) {
        cpa_wait<0>();
        __syncthreads();
        if (it + 1 < iters) issue(it + 1);

        char* base = smem + (it & 1) * GSTAGE_B;
        bf16* Ah = (bf16*)base;
        bf16* Al = (bf16*)(base + 8192);
        bf16* Wh = (bf16*)(base + 16384);
        bf16* Wl = (bf16*)(base + 20736);

        #pragma unroll
        for (int mt = 0; mt < 2; mt++) {
            int t = warpM * 2 + mt;
            wmma::fragment<wmma::matrix_a, 16, 16, 16, bf16, wmma::row_major> ah, al;
            wmma::load_matrix_sync(ah, Ah + t * 256, 16);
            wmma::load_matrix_sync(al, Al + t * 256, 16);
            #pragma unroll
            for (int nj = 0; nj < 4; nj++) {
                wmma::fragment<wmma::matrix_b, 16, 16, 16, bf16, wmma::row_major> bh, bl;
                int boff = warpN * 64 + nj * 16;
                wmma::load_matrix_sync(bh, Wh + boff, 136);
                wmma::load_matrix_sync(bl, Wl + boff, 136);
                wmma::mma_sync(acc[mt][nj], ah, bh, acc[mt][nj]);
                wmma::mma_sync(acc[mt][nj], ah, bl, acc[mt][nj]);
                wmma::mma_sync(acc[mt][nj], al, bh, acc[mt][nj]);
            }
        }
        __syncthreads();
    }

    // epilogue (per-warp staged)
    float* buf = (float*)smem + warp * 320;
    #pragma unroll
    for (int mt = 0; mt < 2; mt++) {
        int t = warpM * 2 + mt;
        #pragma unroll
        for (int nj = 0; nj < 4; nj++) {
            wmma::store_matrix_sync(buf, acc[mt][nj], 20, wmma::mem_row_major);
            __syncwarp();
            #pragma unroll
            for (int l = 0; l < 8; l++) {
                int e = l * 32 + lane;
                int r = e >> 4, c = e & 15;
                int gm = m0 + t * 16 + r;
                int gn = n0 + warpN * 64 + nj * 16 + c;
                float v = buf[r * 20 + c];
                size_t o = (size_t)gm * N + gn;
                if (MODE == 0) {
                    Cf[o] = v;
                    bf16 hi, lo; split_bf16(v, hi, lo);
                    Ch[o] = hi; Cl[o] = lo;
                } else if (MODE == 1) {
                    Cf[o] = v + bias[gn];
                } else {
                    float s = bng[gn] * rsqrtf(1.f + EPS);
                    v = resid[o] + fmaxf(v * s + bnb[gn], 0.f);
                    bf16 hi, lo; split_bf16(v, hi, lo);
                    Ch[o] = hi; Cl[o] = lo;
                }
            }
            __syncwarp();
        }
    }
}

// ---------------- tensor-core 3x3 conv (unchanged from R5) ----------------
#define STAGE_B 43008
__global__ __launch_bounds__(512, 1)
void k_conv_mma(const bf16* __restrict__ in_hi, const bf16* __restrict__ in_lo, int Cin,
                const bf16* __restrict__ w_hi, const bf16* __restrict__ w_lo, int OutC,
                const float* __restrict__ bng, const float* __restrict__ bnb,
                float* __restrict__ out_f,
                bf16* __restrict__ out_hi, bf16* __restrict__ out_lo,
                int out_stride) {
    extern __shared__ char smem[];
    int h0 = blockIdx.x * 4, b = blockIdx.y, n0 = blockIdx.z * 128;
    int tid = threadIdx.x;
    int lane = tid & 31, warp = tid >> 5;
    int warpM = warp >> 1, warpN = warp & 1;
    int csteps = Cin >> 4;
    int iters = 3 * csteps;

    wmma::fragment<wmma::accumulator, 16, 16, 16, float> acc[2][4];
    #pragma unroll
    for (int mt = 0; mt < 2; mt++)
        #pragma unroll
        for (int nj = 0; nj < 4; nj++) wmma::fill_fragment(acc[mt][nj], 0.f);

    auto issue = [&](int it) {
        int ky = it / csteps;
        int c0 = (it - ky * csteps) << 4;
        char* base = smem + (it & 1) * STAGE_B;
        bf16* Ah = (bf16*)base;
        bf16* Al = (bf16*)(base + 8448);
        bf16* Wh = (bf16*)(base + 16896);
        bf16* Wl = (bf16*)(base + 29952);
        for (int u = tid; u < 1056; u += 512) {
            int v = (u < 528) ? u : u - 528;
            int flat = v * 8;
            int r = flat / 1056, rem = flat % 1056;
            int wi = rem >> 4, c8 = rem & 15;
            int gh = h0 + r + ky - 1, gw = wi - 1;
            bool pred = (gh >= 0 && gh < HH && gw >= 0 && gw < WW);
            const bf16* src = (u < 528) ? in_hi : in_lo;
            const bf16* g = pred ? (src + ((size_t)(b * HH + gh) * WW + gw) * Cin + c0 + c8) : src;
            bf16* dst = ((u < 528) ? Ah : Al) + (r * 66 + wi) * 16 + c8;
            cpa16(dst, g, pred);
        }
        for (int u = tid; u < 1536; u += 512) {
            int v = (u < 768) ? u : u - 768;
            int flat = v * 8;
            int kx = flat >> 11, rem = flat & 2047;
            int ck = rem >> 7, o8 = rem & 127;
            const bf16* src = (u < 768) ? w_hi : w_lo;
            const bf16* g = src + ((size_t)(ky * 3 + kx) * Cin + c0 + ck) * OutC + n0 + o8;
            bf16* dst = ((u < 768) ? Wh : Wl) + kx * 2176 + ck * 136 + o8;
            cpa16(dst, g, true);
        }
        cpa_commit();
    };

    issue(0);

    for (int it = 0; it < iters; it++) {
        cpa_wait<0>();
        __syncthreads();
        if (it + 1 < iters) issue(it + 1);

        char* base = smem + (it & 1) * STAGE_B;
        bf16* Ah = (bf16*)base;
        bf16* Al = (bf16*)(base + 8448);
        bf16* Wh = (bf16*)(base + 16896);
        bf16* Wl = (bf16*)(base + 29952);

        #pragma unroll
        for (int mt = 0; mt < 2; mt++) {
            int t = warpM * 2 + mt;
            int pbase = (t >> 2) * 66 + (t & 3) * 16;
            #pragma unroll
            for (int kx = 0; kx < 3; kx++) {
                wmma::fragment<wmma::matrix_a, 16, 16, 16, bf16, wmma::row_major> ah, al;
                wmma::load_matrix_sync(ah, Ah + (pbase + kx) * 16, 16);
                wmma::load_matrix_sync(al, Al + (pbase + kx) * 16, 16);
                #pragma unroll
                for (int nj = 0; nj < 4; nj++) {
                    wmma::fragment<wmma::matrix_b, 16, 16, 16, bf16, wmma::row_major> bh, bl;
                    int boff = kx * 2176 + warpN * 64 + nj * 16;
                    wmma::load_matrix_sync(bh, Wh + boff, 136);
                    wmma::load_matrix_sync(bl, Wl + boff, 136);
                    wmma::mma_sync(acc[mt][nj], ah, bh, acc[mt][nj]);
                    wmma::mma_sync(acc[mt][nj], ah, bl, acc[mt][nj]);
                    wmma::mma_sync(acc[mt][nj], al, bh, acc[mt][nj]);
                }
            }
        }
        __syncthreads();
    }

    float* buf = (float*)smem + warp * 320;
    #pragma unroll
    for (int mt = 0; mt < 2; mt++) {
        int t = warpM * 2 + mt;
        int row_l = t >> 2, px0 = (t & 3) * 16;
        size_t rowbase = (size_t)(b * HH + h0 + row_l) * WW;
        #pragma unroll
        for (int nj = 0; nj < 4; nj++) {
            wmma::store_matrix_sync(buf, acc[mt][nj], 20, wmma::mem_row_major);
            __syncwarp();
            #pragma unroll
            for (int l = 0; l < 8; l++) {
                int e = l * 32 + lane;
                int r = e >> 4, c = e & 15;
                int gn = n0 + warpN * 64 + nj * 16 + c;
                float v = buf[r * 20 + c];
                float s = bng[gn] * rsqrtf(1.f + EPS);
                v = fmaxf(v * s + bnb[gn], 0.f);
                size_t o = (rowbase + px0 + r) * out_stride + gn;
                if (out_f) {
                    out_f[o] = v;
                } else {
                    bf16 hi, lo; split_bf16(v, hi, lo);
                    out_hi[o] = hi; out_lo[o] = lo;
                }
            }
            __syncwarp();
        }
    }
}

// ---------------- final 1x1 classifier -> NCHW ----------------
__global__ void k_classifier(const float* __restrict__ drop_w, float* __restrict__ out) {
    __shared__ float Xs[32][65];
    __shared__ float Ws[KK][33];
    int tid = threadIdx.x;
    int row0 = blockIdx.x * 64;
    int b = row0 >> 12;
    int hw0 = row0 & 4095;
    float acc[5] = {0.f, 0.f, 0.f, 0.f, 0.f};

    for (int c0 = 0; c0 < CC; c0 += 32) {
        for (int idx = tid; idx < 64 * 32; idx += 256) {
            int r = idx >> 5, cc = idx & 31;
            Xs[cc][r] = g_x3[(size_t)(row0 + r) * CC + c0 + cc];
        }
        for (int idx = tid; idx < KK * 32; idx += 256) {
            int k = idx >> 5, cc = idx & 31;
            Ws[k][cc] = drop_w[(size_t)k * CC + c0 + cc];
        }
        __syncthreads();
        #pragma unroll
        for (int sIdx = 0; sIdx < 5; sIdx++) {
            int o = tid + sIdx * 256;
            if (o < KK * 64) {
                int k = o >> 6, r = o & 63;
                float a = acc[sIdx];
                #pragma unroll 8
                for (int cc = 0; cc < 32; cc++) a += Ws[k][cc] * Xs[cc][r];
                acc[sIdx] = a;
            }
        }
        __syncthreads();
    }
    #pragma unroll
    for (int sIdx = 0; sIdx < 5; sIdx++) {
        int o = tid + sIdx * 256;
        if (o < KK * 64) {
            int k = o >> 6, r = o & 63;
            out[((size_t)b * KK + k) * HW + hw0 + r] = acc[sIdx];
        }
    }
}

// ---------------- launch ----------------
extern "C" void kernel_launch(void* const* d_in, const int* in_sizes, int n_in,
                              void* d_out, int out_size) {
    const float* M_1   = (const float*)d_in[0];
    const float* F     = (const float*)d_in[1];
    const float* I     = (const float*)d_in[2];
    const float* R     = (const float*)d_in[3];
    const float* lg_w1 = (const float*)d_in[4];
    const float* lg_w2 = (const float*)d_in[5];
    const float* fuse_w= (const float*)d_in[6];
    const float* fuse_b= (const float*)d_in[7];
    const float* q_w   = (const float*)d_in[8];
    const float* q_b   = (const float*)d_in[9];
    const float* k_w   = (const float*)d_in[10];
    const float* k_b   = (const float*)d_in[11];
    const float* v_w   = (const float*)d_in[12];
    const float* v_b   = (const float*)d_in[13];
    const float* c1_w  = (const float*)d_in[14];
    const float* bn1_g = (const float*)d_in[15];
    const float* bn1_b = (const float*)d_in[16];
    const float* c2_w  = (const float*)d_in[17];
    const float* bn2_g = (const float*)d_in[18];
    const float* bn2_b = (const float*)d_in[19];
    const float* c3_w  = (const float*)d_in[20];
    const float* bn3_g = (const float*)d_in[21];
    const float* bn3_b = (const float*)d_in[22];
    const float* drop_w= (const float*)d_in[23];
    float* out = (float*)d_out;

    float *p_Fnhwc, *p_Fl, *p_Fl2, *p_Fg, *p_q, *p_k, *p_v, *p_x3;
    bf16 *p_Fh, *p_Flo, *p_hh, *p_hl, *p_Fl2h, *p_Fl2l, *p_Fsh, *p_Fsl;
    bf16 *p_cath, *p_catl, *p_Fo1h, *p_Fo1l;
    bf16 *p_w2h, *p_w2l, *p_w3h, *p_w3l;
    bf16 *p_qwh, *p_qwl, *p_kwh, *p_kwl, *p_lgwh, *p_lgwl, *p_c1h, *p_c1l;
    cudaGetSymbolAddress((void**)&p_Fnhwc, g_Fnhwc);
    cudaGetSymbolAddress((void**)&p_Fl,    g_Fl);
    cudaGetSymbolAddress((void**)&p_Fl2,   g_Fl2);
    cudaGetSymbolAddress((void**)&p_Fg,    g_Fg);
    cudaGetSymbolAddress((void**)&p_q,     g_query);
    cudaGetSymbolAddress((void**)&p_k,     g_key);
    cudaGetSymbolAddress((void**)&p_v,     g_value);
    cudaGetSymbolAddress((void**)&p_x3,    g_x3);
    cudaGetSymbolAddress((void**)&p_Fh,    g_Fh);
    cudaGetSymbolAddress((void**)&p_Flo,   g_Flo);
    cudaGetSymbolAddress((void**)&p_hh,    g_hh);
    cudaGetSymbolAddress((void**)&p_hl,    g_hl);
    cudaGetSymbolAddress((void**)&p_Fl2h,  g_Fl2h);
    cudaGetSymbolAddress((void**)&p_Fl2l,  g_Fl2l);
    cudaGetSymbolAddress((void**)&p_Fsh,   g_Fsh);
    cudaGetSymbolAddress((void**)&p_Fsl,   g_Fsl);
    cudaGetSymbolAddress((void**)&p_cath,  g_cath);
    cudaGetSymbolAddress((void**)&p_catl,  g_catl);
    cudaGetSymbolAddress((void**)&p_Fo1h,  g_Fo1h);
    cudaGetSymbolAddress((void**)&p_Fo1l,  g_Fo1l);
    cudaGetSymbolAddress((void**)&p_w2h,   g_w2h);
    cudaGetSymbolAddress((void**)&p_w2l,   g_w2l);
    cudaGetSymbolAddress((void**)&p_w3h,   g_w3h);
    cudaGetSymbolAddress((void**)&p_w3l,   g_w3l);
    cudaGetSymbolAddress((void**)&p_qwh,   g_qwh);
    cudaGetSymbolAddress((void**)&p_qwl,   g_qwl);
    cudaGetSymbolAddress((void**)&p_kwh,   g_kwh);
    cudaGetSymbolAddress((void**)&p_kwl,   g_kwl);
    cudaGetSymbolAddress((void**)&p_lgwh,  g_lgwh);
    cudaGetSymbolAddress((void**)&p_lgwl,  g_lgwl);
    cudaGetSymbolAddress((void**)&p_c1h,   g_c1h);
    cudaGetSymbolAddress((void**)&p_c1l,   g_c1l);

    dim3 blk32(32, 8);
    const int CONV_SMEM = 2 * STAGE_B;     // 86016 B
    const int GEMM_SMEM = 2 * GSTAGE_B;    // 50176 B
    cudaFuncSetAttribute(k_conv_mma, cudaFuncAttributeMaxDynamicSharedMemorySize, CONV_SMEM);
    cudaFuncSetAttribute(k_gemm_mma<0>, cudaFuncAttributeMaxDynamicSharedMemorySize, GEMM_SMEM);
    cudaFuncSetAttribute(k_gemm_mma<1>, cudaFuncAttributeMaxDynamicSharedMemorySize, GEMM_SMEM);
    cudaFuncSetAttribute(k_gemm_mma<2>, cudaFuncAttributeMaxDynamicSharedMemorySize, GEMM_SMEM);

    // weight prep
    k_wsplit<<<(512 * 512 * 9 + 255) / 256, 256>>>(c2_w, p_w2h, p_w2l, 512, 512);
    k_wsplit<<<(512 * 2560 * 9 + 255) / 256, 256>>>(c3_w, p_w3h, p_w3l, 512, 2560);
    k_wtsplit<<<(512 * 256 + 255) / 256, 256>>>(q_w, p_qwh, p_qwl, 512, 256);
    k_wtsplit<<<(512 * 256 + 255) / 256, 256>>>(k_w, p_kwh, p_kwl, 512, 256);
    k_wtsplit<<<(512 * 512 + 255) / 256, 256>>>(lg_w2, p_lgwh, p_lgwl, 512, 512);
    k_wtsplit<<<(256 * 512 + 255) / 256, 256>>>(c1_w, p_c1h, p_c1l, 256, 512);

    // activations prep
    k_transpose_f<<<dim3(HW / 32, CC / 32, BATCH), blk32>>>(F, p_Fnhwc, p_Fh, p_Flo);
    k_transpose_pair<<<dim3(HW / 32, 2048 / 32, BATCH), blk32>>>(M_1, p_cath, p_catl, 2048, CIN3, CC);
    k_patch_fl<<<BATCH * PP, 256>>>(I, R);
    k_lg1<<<dim3(CC / 64, BATCH * KK), 256>>>(lg_w1);

    // Fl2 = h @ lg_w2^T : [4864,512] x [512,512]
    k_gemm_mma<0><<<dim3(512 / 128, 4864 / 256), 512, GEMM_SMEM>>>(
        p_hh, p_hl, p_lgwh, p_lgwl, 512, 512, p_Fl2, p_Fl2h, p_Fl2l,
        nullptr, nullptr, nullptr, nullptr);
    k_fuse<<<BATCH * KK, CC>>>(fuse_w, fuse_b);

    // query = F @ q_w^T + q_b : [16384,512] x [512,256]
    k_gemm_mma<1><<<dim3(256 / 128, 16384 / 256), 512, GEMM_SMEM>>>(
        p_Fh, p_Flo, p_qwh, p_qwl, 512, 256, p_q, nullptr, nullptr,
        q_b, nullptr, nullptr, nullptr);
    // key = Fl2 @ k_w^T + k_b : [4864,512] x [512,256]
    k_gemm_mma<1><<<dim3(256 / 128, 4864 / 256), 512, GEMM_SMEM>>>(
        p_Fl2h, p_Fl2l, p_kwh, p_kwl, 512, 256, p_k, nullptr, nullptr,
        k_b, nullptr, nullptr, nullptr);
    // value (tiny, fp32 SIMT)
    k_gemm_v<<<dim3(DD / 64, (BATCH * KK + 63) / 64), 256>>>(
        p_Fg, v_w, p_v, BATCH * KK, DD, CC, v_b);

    k_attn<<<BATCH * PP, 256>>>();

    // Fo1 = F + relu(bn1(F_s @ c1_w^T)) : [16384,256] x [256,512] -> pair
    k_gemm_mma<2><<<dim3(512 / 128, 16384 / 256), 512, GEMM_SMEM>>>(
        p_Fsh, p_Fsl, p_c1h, p_c1l, 256, 512, nullptr, p_Fo1h, p_Fo1l,
        nullptr, bn1_g, bn1_b, p_Fnhwc);

    // conv2: Fo1(512) -> cat[:,0:512) bf16 pair
    k_conv_mma<<<dim3(HH / 4, BATCH, 4), 512, CONV_SMEM>>>(
        p_Fo1h, p_Fo1l, CC, p_w2h, p_w2l, 512, bn2_g, bn2_b,
        nullptr, p_cath, p_catl, CIN3);
    // conv3: cat(2560) -> x3 fp32
    k_conv_mma<<<dim3(HH / 4, BATCH, 4), 512, CONV_SMEM>>>(
        p_cath, p_catl, CIN3, p_w3h, p_w3l, 512, bn3_g, bn3_b,
        p_x3, nullptr, nullptr, CC);

    k_classifier<<<(BATCH * HW) / 64, 256>>>(drop_w, out);
}

// round 9
// speedup vs baseline: 1.2258x; 1.2258x over previous
#include <cuda_runtime.h>
#include <cuda_bf16.h>
#include <mma.h>
#include <math.h>
#include <stdint.h>

using namespace nvcuda;
typedef __nv_bfloat16 bf16;

#define EPS 1e-5f
#define BATCH 4
#define HH 64
#define WW 64
#define HW 4096
#define BHW 16384
#define CC 512
#define KK 19
#define PP 64
#define NN 64
#define DD 256
#define CIN3 2560

__device__ float g_Fnhwc[BATCH * HW * CC];
__device__ float g_Fl[BATCH * PP * KK * CC];
__device__ float g_Fl2[BATCH * PP * KK * CC];
__device__ float g_Fg[BATCH * KK * CC];
__device__ float g_query[BATCH * HW * DD];
__device__ float g_key[BATCH * PP * KK * DD];
__device__ float g_value[BATCH * KK * DD];
__device__ float g_x3[BATCH * HW * CC];

__device__ bf16 g_Fh[BATCH * HW * CC];
__device__ bf16 g_Flo[BATCH * HW * CC];
__device__ bf16 g_hh[BATCH * PP * KK * CC];
__device__ bf16 g_hl[BATCH * PP * KK * CC];
__device__ bf16 g_Fl2h[BATCH * PP * KK * CC];
__device__ bf16 g_Fl2l[BATCH * PP * KK * CC];
__device__ bf16 g_Fsh[BATCH * HW * DD];
__device__ bf16 g_Fsl[BATCH * HW * DD];

// channel-blocked activations: [chunk][B][H][W][16]
__device__ bf16 g_Fo1bh[32 * BHW * 16];
__device__ bf16 g_Fo1bl[32 * BHW * 16];
__device__ bf16 g_catbh[(size_t)160 * BHW * 16];
__device__ bf16 g_catbl[(size_t)160 * BHW * 16];

// conv weights blocked for bulk copy: [ntile(4)][chunk][term(2)][tap9][k16][136]
__device__ bf16 g_w2b[4 * 32 * 2 * 19584];
__device__ bf16 g_w3b[(size_t)4 * 160 * 2 * 19584];

// GEMM weights [K][N]
__device__ bf16 g_qwh[512 * 256], g_qwl[512 * 256];
__device__ bf16 g_kwh[512 * 256], g_kwl[512 * 256];
__device__ bf16 g_lgwh[512 * 512], g_lgwl[512 * 512];
__device__ bf16 g_c1h[256 * 512], g_c1l[256 * 512];

__device__ __forceinline__ void split_bf16(float v, bf16& hi, bf16& lo) {
    hi = __float2bfloat16(v);
    lo = __float2bfloat16(v - __bfloat162float(hi));
}
__device__ __forceinline__ void cpa16(void* sdst, const void* gsrc, bool pred) {
    unsigned int s = (unsigned int)__cvta_generic_to_shared(sdst);
    int sz = pred ? 16 : 0;
    asm volatile("cp.async.cg.shared.global [%0], [%1], 16, %2;" :: "r"(s), "l"(gsrc), "r"(sz));
}
__device__ __forceinline__ void cpa_commit() { asm volatile("cp.async.commit_group;"); }
template <int N>
__device__ __forceinline__ void cpa_wait() { asm volatile("cp.async.wait_group %0;" :: "n"(N)); }

// ---- bulk copy + mbarrier ----
__device__ __forceinline__ void bulk_cp(unsigned int sdst, const void* gsrc,
                                        unsigned int bytes, unsigned int mbar) {
    asm volatile(
        "cp.async.bulk.shared::cta.global.mbarrier::complete_tx::bytes [%0], [%1], %2, [%3];"
        :: "r"(sdst), "l"(gsrc), "r"(bytes), "r"(mbar) : "memory");
}
__device__ __forceinline__ void mbar_init(unsigned int m, unsigned int c) {
    asm volatile("mbarrier.init.shared.b64 [%0], %1;" :: "r"(m), "r"(c) : "memory");
}
__device__ __forceinline__ void mbar_expect(unsigned int m, unsigned int tx) {
    asm volatile("mbarrier.arrive.expect_tx.shared.b64 _, [%0], %1;" :: "r"(m), "r"(tx) : "memory");
}
__device__ __forceinline__ void mbar_wait(unsigned int m, unsigned int par) {
    unsigned int done;
    asm volatile(
        "{\n\t.reg .pred p;\n\t"
        "mbarrier.try_wait.parity.acquire.cta.shared::cta.b64 p, [%1], %2;\n\t"
        "selp.b32 %0, 1, 0, p;\n\t}" : "=r"(done) : "r"(m), "r"(par) : "memory");
    if (!done) {
        asm volatile(
            "{\n\t.reg .pred P1;\n\tWL_%=:\n\t"
            "mbarrier.try_wait.parity.acquire.cta.shared::cta.b64 P1, [%0], %1, 0x989680;\n\t"
            "@P1 bra.uni WD_%=;\n\tbra.uni WL_%=;\n\tWD_%=:\n\t}"
            :: "r"(m), "r"(par) : "memory");
    }
}

// ---------------- transposes ----------------
__global__ void k_transpose_f(const float* __restrict__ in, float* __restrict__ out,
                              bf16* __restrict__ oh, bf16* __restrict__ ol) {
    __shared__ float tile[32][33];
    int b = blockIdx.z, hw0 = blockIdx.x * 32, c0 = blockIdx.y * 32;
    int tx = threadIdx.x, ty = threadIdx.y;
    for (int i = ty; i < 32; i += 8)
        tile[i][tx] = in[((size_t)b * CC + c0 + i) * HW + hw0 + tx];
    __syncthreads();
    for (int i = ty; i < 32; i += 8) {
        float v = tile[tx][i];
        size_t o = ((size_t)b * HW + hw0 + i) * CC + c0 + tx;
        out[o] = v;
        bf16 hi, lo; split_bf16(v, hi, lo);
        oh[o] = hi; ol[o] = lo;
    }
}
// M_1 -> cat blocked chunks 32..159
__global__ void k_transpose_m1(const float* __restrict__ in, bf16* __restrict__ oh,
                               bf16* __restrict__ ol) {
    __shared__ float tile[32][33];
    int b = blockIdx.z, hw0 = blockIdx.x * 32, c0 = blockIdx.y * 32;
    int tx = threadIdx.x, ty = threadIdx.y;
    for (int i = ty; i < 32; i += 8)
        tile[i][tx] = in[((size_t)b * 2048 + c0 + i) * HW + hw0 + tx];
    __syncthreads();
    for (int i = ty; i < 32; i += 8) {
        float v = tile[tx][i];
        bf16 hi, lo; split_bf16(v, hi, lo);
        int cg = 512 + c0 + tx;
        size_t o = ((size_t)(cg >> 4) * BHW + (size_t)b * HW + hw0 + i) * 16 + (cg & 15);
        oh[o] = hi; ol[o] = lo;
    }
}

// conv weight prep: OIHW -> [ntile][chunk][term][tap9][k16][136]
__global__ void k_wprep(const float* __restrict__ w, bf16* __restrict__ dst,
                        int Cin, int csteps) {
    size_t d = (size_t)blockIdx.x * 256 + threadIdx.x;
    size_t total = (size_t)4 * csteps * 2 * 19584;
    if (d >= total) return;
    int oc = d % 136;
    size_t r = d / 136;
    int k = r % 16; r /= 16;
    int tap = r % 9; r /= 9;
    int t = r & 1; r >>= 1;
    int ch = r % csteps;
    int nt = r / csteps;
    bf16 outv = __float2bfloat16(0.f);
    if (oc < 128) {
        int o = nt * 128 + oc;
        int ci = ch * 16 + k;
        float v = w[((size_t)o * Cin + ci) * 9 + tap];
        bf16 hi, lo; split_bf16(v, hi, lo);
        outv = t ? lo : hi;
    }
    dst[d] = outv;
}
__global__ void k_wtsplit(const float* __restrict__ w, bf16* __restrict__ oh,
                          bf16* __restrict__ ol, int K, int N) {
    int d = blockIdx.x * 256 + threadIdx.x;
    if (d >= K * N) return;
    int k = d / N, n = d % N;
    float v = w[(size_t)n * K + k];
    bf16 hi, lo; split_bf16(v, hi, lo);
    oh[d] = hi; ol[d] = lo;
}

// ---------------- patch softmax + F_l ----------------
__global__ void k_patch_fl(const float* __restrict__ I, const float* __restrict__ R) {
    int bp = blockIdx.x, b = bp >> 6, p = bp & 63;
    int ph = p >> 3, pw = p & 7, tid = threadIdx.x;
    __shared__ float lg[KK][NN];
    __shared__ float pix[NN][20];
    __shared__ float bc[KK];
    __shared__ float Fp[NN][65];
    for (int idx = tid; idx < KK * NN; idx += 256) {
        int k = idx / NN, n = idx % NN;
        int h = ph * 8 + (n >> 3), w = pw * 8 + (n & 7);
        lg[k][n] = I[(((size_t)b * KK + k) * HH + h) * WW + w];
    }
    if (tid < KK) bc[tid] = R[((size_t)b * KK + tid) * PP + p];
    __syncthreads();
    if (tid < KK) {
        float mx = -1e30f;
        for (int n = 0; n < NN; n++) mx = fmaxf(mx, lg[tid][n]);
        float s = 0.f;
        for (int n = 0; n < NN; n++) { float e = __expf(lg[tid][n] - mx); pix[n][tid] = e; s += e; }
        float inv = 1.f / s;
        for (int n = 0; n < NN; n++) pix[n][tid] *= inv;
    }
    __syncthreads();
    for (int c0 = 0; c0 < CC; c0 += 64) {
        for (int idx = tid; idx < NN * 64; idx += 256) {
            int n = idx >> 6, cc = idx & 63;
            int h = ph * 8 + (n >> 3), w = pw * 8 + (n & 7);
            Fp[n][cc] = g_Fnhwc[((size_t)b * HW + h * WW + w) * CC + c0 + cc];
        }
        __syncthreads();
        for (int o = tid; o < KK * 64; o += 256) {
            int k = o >> 6, cc = o & 63;
            float acc = 0.f;
            #pragma unroll 8
            for (int n = 0; n < NN; n++) acc += pix[n][k] * Fp[n][cc];
            g_Fl[((size_t)bp * KK + k) * CC + c0 + cc] = acc * bc[k];
        }
        __syncthreads();
    }
}

__global__ void k_lg1(const float* __restrict__ lg_w1) {
    int c0 = blockIdx.x * 64, bk = blockIdx.y;
    int b = bk / KK, k = bk % KK, tid = threadIdx.x;
    __shared__ float w1[64][64];
    __shared__ float Fl[64][65];
    for (int idx = tid; idx < 4096; idx += 256) w1[idx >> 6][idx & 63] = lg_w1[idx];
    for (int idx = tid; idx < 4096; idx += 256) {
        int p = idx >> 6, cc = idx & 63;
        Fl[p][cc] = g_Fl[(((size_t)b * PP + p) * KK + k) * CC + c0 + cc];
    }
    __syncthreads();
    for (int o = tid; o < 4096; o += 256) {
        int q = o >> 6, cc = o & 63;
        float acc = Fl[q][cc];
        #pragma unroll 8
        for (int p = 0; p < 64; p++) acc += w1[q][p] * Fl[p][cc];
        float v = fmaxf(acc, 0.f);
        bf16 hi, lo; split_bf16(v, hi, lo);
        size_t oi = (((size_t)b * PP + q) * KK + k) * CC + c0 + cc;
        g_hh[oi] = hi; g_hl[oi] = lo;
    }
}

__global__ void k_gemm_v(const float* __restrict__ A, const float* __restrict__ Bw,
                         float* __restrict__ C, int M, int N, int K,
                         const float* __restrict__ bias) {
    __shared__ float As[16][68];
    __shared__ float Bs[16][68];
    int m0 = blockIdx.y * 64, n0 = blockIdx.x * 64, tid = threadIdx.x;
    int tx = tid & 15, ty = tid >> 4;
    float acc[4][4] = {};
    for (int k0 = 0; k0 < K; k0 += 16) {
        for (int idx = tid; idx < 1024; idx += 256) {
            int i = idx >> 4, kk = idx & 15;
            int m = m0 + i;
            As[kk][i] = (m < M) ? A[(size_t)m * K + k0 + kk] : 0.f;
        }
        for (int idx = tid; idx < 1024; idx += 256) {
            int j = idx >> 4, kk = idx & 15;
            Bs[kk][j] = Bw[(size_t)(n0 + j) * K + k0 + kk];
        }
        __syncthreads();
        #pragma unroll
        for (int kk = 0; kk < 16; kk++) {
            float a[4], bv[4];
            #pragma unroll
            for (int i = 0; i < 4; i++) a[i] = As[kk][ty * 4 + i];
            #pragma unroll
            for (int j = 0; j < 4; j++) bv[j] = Bs[kk][tx * 4 + j];
            #pragma unroll
            for (int i = 0; i < 4; i++)
                #pragma unroll
                for (int j = 0; j < 4; j++) acc[i][j] += a[i] * bv[j];
        }
        __syncthreads();
    }
    #pragma unroll
    for (int i = 0; i < 4; i++) {
        int m = m0 + ty * 4 + i;
        if (m >= M) continue;
        #pragma unroll
        for (int j = 0; j < 4; j++)
            C[(size_t)m * N + n0 + tx * 4 + j] = acc[i][j] + bias[n0 + tx * 4 + j];
    }
}

__global__ void k_fuse(const float* __restrict__ fw, const float* __restrict__ fb) {
    int bk = blockIdx.x, c = threadIdx.x;
    int b = bk / KK, k = bk % KK;
    float acc = fb[0];
    #pragma unroll 8
    for (int p = 0; p < PP; p++)
        acc += fw[p] * g_Fl2[(((size_t)b * PP + p) * KK + k) * CC + c];
    g_Fg[(size_t)bk * CC + c] = acc;
}

__global__ void k_attn() {
    int bp = blockIdx.x, b = bp >> 6, p = bp & 63;
    int ph = p >> 3, pw = p & 7, tid = threadIdx.x;
    __shared__ float ks[KK][DD];
    __shared__ float vs[KK][DD];
    for (int idx = tid; idx < KK * DD; idx += 256)
        ((float*)ks)[idx] = g_key[(size_t)bp * KK * DD + idx];
    for (int idx = tid; idx < KK * DD; idx += 256)
        ((float*)vs)[idx] = g_value[(size_t)b * KK * DD + idx];
    __syncthreads();
    int warp = tid >> 5, lane = tid & 31;
    for (int n = warp; n < NN; n += 8) {
        int h = ph * 8 + (n >> 3), w = pw * 8 + (n & 7);
        const float* qrow = &g_query[((size_t)b * HW + h * WW + w) * DD];
        float qr[8];
        #pragma unroll
        for (int i = 0; i < 8; i++) qr[i] = qrow[i * 32 + lane];
        float acc[KK];
        #pragma unroll
        for (int k = 0; k < KK; k++) acc[k] = 0.f;
        #pragma unroll
        for (int i = 0; i < 8; i++) {
            float qd = qr[i];
            #pragma unroll
            for (int k = 0; k < KK; k++) acc[k] += qd * ks[k][i * 32 + lane];
        }
        #pragma unroll
        for (int k = 0; k < KK; k++)
            #pragma unroll
            for (int off = 16; off > 0; off >>= 1)
                acc[k] += __shfl_xor_sync(0xFFFFFFFFu, acc[k], off);
        float mx = -1e30f;
        #pragma unroll
        for (int k = 0; k < KK; k++) mx = fmaxf(mx, acc[k]);
        float sum = 0.f;
        #pragma unroll
        for (int k = 0; k < KK; k++) { acc[k] = __expf(acc[k] - mx); sum += acc[k]; }
        float inv = 1.f / sum;
        #pragma unroll
        for (int k = 0; k < KK; k++) acc[k] *= inv;
        size_t ob = ((size_t)b * HW + h * WW + w) * DD;
        #pragma unroll
        for (int i = 0; i < 8; i++) {
            int d = i * 32 + lane;
            float o = 0.f;
            #pragma unroll
            for (int k = 0; k < KK; k++) o += acc[k] * vs[k][d];
            bf16 hi, lo; split_bf16(o, hi, lo);
            g_Fsh[ob + d] = hi; g_Fsl[ob + d] = lo;
        }
    }
}

// ---------------- split-bf16 wmma GEMM (MODE2 writes blocked) ----------------
#define GSTAGE_B 25088
template <int MODE>
__global__ __launch_bounds__(512)
void k_gemm_mma(const bf16* __restrict__ Ahg, const bf16* __restrict__ Alg,
                const bf16* __restrict__ Wth, const bf16* __restrict__ Wtl,
                int K, int N,
                float* __restrict__ Cf, bf16* __restrict__ Ch, bf16* __restrict__ Cl,
                const float* __restrict__ bias,
                const float* __restrict__ bng, const float* __restrict__ bnb,
                const float* __restrict__ resid) {
    extern __shared__ char smem[];
    int n0 = blockIdx.x * 128, m0 = blockIdx.y * 256;
    int tid = threadIdx.x, lane = tid & 31, warp = tid >> 5;
    int warpM = warp >> 1, warpN = warp & 1;
    int iters = K >> 4;

    wmma::fragment<wmma::accumulator, 16, 16, 16, float> acc[2][4];
    #pragma unroll
    for (int mt = 0; mt < 2; mt++)
        #pragma unroll
        for (int nj = 0; nj < 4; nj++) wmma::fill_fragment(acc[mt][nj], 0.f);

    auto issue = [&](int it) {
        int k0 = it << 4;
        char* base = smem + (it & 1) * GSTAGE_B;
        bf16* Ah = (bf16*)base;
        bf16* Al = (bf16*)(base + 8192);
        bf16* Wh = (bf16*)(base + 16384);
        bf16* Wl = (bf16*)(base + 20736);
        for (int u = tid; u < 1024; u += 512) {
            int v = (u < 512) ? u : u - 512;
            int flat = v * 8;
            int r = flat >> 4, c8 = flat & 15;
            const bf16* src = (u < 512) ? Ahg : Alg;
            cpa16(((u < 512) ? Ah : Al) + flat, src + (size_t)(m0 + r) * K + k0 + c8, true);
        }
        if (tid < 512) {
            int u = tid;
            if (u < 512) {
                int v = (u < 256) ? u : u - 256;
                int flat = v * 8;
                int kk = flat >> 7, n8 = flat & 127;
                const bf16* src = (u < 256) ? Wth : Wtl;
                cpa16(((u < 256) ? Wh : Wl) + kk * 136 + n8,
                      src + (size_t)(k0 + kk) * N + n0 + n8, true);
            }
        }
        cpa_commit();
    };

    issue(0);
    for (int it = 0; it < iters; it++) {
        cpa_wait<0>();
        __syncthreads();
        if (it + 1 < iters) issue(it + 1);
        char* base = smem + (it & 1) * GSTAGE_B;
        bf16* Ah = (bf16*)base;
        bf16* Al = (bf16*)(base + 8192);
        bf16* Wh = (bf16*)(base + 16384);
        bf16* Wl = (bf16*)(base + 20736);
        #pragma unroll
        for (int mt = 0; mt < 2; mt++) {
            int t = warpM * 2 + mt;
            wmma::fragment<wmma::matrix_a, 16, 16, 16, bf16, wmma::row_major> ah, al;
            wmma::load_matrix_sync(ah, Ah + t * 256, 16);
            wmma::load_matrix_sync(al, Al + t * 256, 16);
            #pragma unroll
            for (int nj = 0; nj < 4; nj++) {
                wmma::fragment<wmma::matrix_b, 16, 16, 16, bf16, wmma::row_major> bh, bl;
                int boff = warpN * 64 + nj * 16;
                wmma::load_matrix_sync(bh, Wh + boff, 136);
                wmma::load_matrix_sync(bl, Wl + boff, 136);
                wmma::mma_sync(acc[mt][nj], ah, bh, acc[mt][nj]);
                wmma::mma_sync(acc[mt][nj], ah, bl, acc[mt][nj]);
                wmma::mma_sync(acc[mt][nj], al, bh, acc[mt][nj]);
            }
        }
        __syncthreads();
    }

    float* buf = (float*)smem + warp * 320;
    #pragma unroll
    for (int mt = 0; mt < 2; mt++) {
        int t = warpM * 2 + mt;
        #pragma unroll
        for (int nj = 0; nj < 4; nj++) {
            wmma::store_matrix_sync(buf, acc[mt][nj], 20, wmma::mem_row_major);
            __syncwarp();
            #pragma unroll
            for (int l = 0; l < 8; l++) {
                int e = l * 32 + lane;
                int r = e >> 4, c = e & 15;
                int gm = m0 + t * 16 + r;
                int gn = n0 + warpN * 64 + nj * 16 + c;
                float v = buf[r * 20 + c];
                size_t o = (size_t)gm * N + gn;
                if (MODE == 0) {
                    Cf[o] = v;
                    bf16 hi, lo; split_bf16(v, hi, lo);
                    Ch[o] = hi; Cl[o] = lo;
                } else if (MODE == 1) {
                    Cf[o] = v + bias[gn];
                } else {
                    float s = bng[gn] * rsqrtf(1.f + EPS);
                    v = resid[o] + fmaxf(v * s + bnb[gn], 0.f);
                    bf16 hi, lo; split_bf16(v, hi, lo);
                    size_t bo = ((size_t)(gn >> 4) * BHW + gm) * 16 + (gn & 15);
                    Ch[bo] = hi; Cl[bo] = lo;
                }
            }
            __syncwarp();
        }
    }
}

// ---------------- bulk-copy HMMA 3x3 conv ----------------
// block: 256 px (4 rows) x 128 oc; 512 thr (16 warps: 8 warpM x 2 warpN)
// stage (bytes): Ah[6][66][16]=12672 | Al=12672 | Wh[9][16][136]=39168 | Wl=39168 = 103680
#define SA_L 12672
#define SW_H 25344
#define SW_L 64512
#define CSTG 103680
#define CONVB_SMEM (2 * CSTG + 64)
__global__ __launch_bounds__(512, 1)
void k_conv_bulk(const bf16* __restrict__ inh, const bf16* __restrict__ inl, int csteps,
                 const bf16* __restrict__ wb,
                 const float* __restrict__ bng, const float* __restrict__ bnb,
                 float* __restrict__ out_f, bf16* __restrict__ obh, bf16* __restrict__ obl) {
    extern __shared__ char dsm[];
    char* aptr = (char*)(((size_t)dsm + 127) & ~(size_t)127);
    unsigned int abase = (unsigned int)__cvta_generic_to_shared(aptr);
    unsigned int mb0 = abase + 2 * CSTG, mb1 = mb0 + 8;

    int tid = threadIdx.x, lane = tid & 31, warp = tid >> 5;
    int warpM = warp >> 1, warpN = warp & 1;
    int b = blockIdx.x >> 4, h0 = (blockIdx.x & 15) << 2;
    int nt = blockIdx.y;
    int oc0 = nt << 7;

    if (tid == 0) { mbar_init(mb0, 1); mbar_init(mb1, 1); }
    // zero-once: halo cols px0/px65 all rows + fully-invalid rows, both arrays, both buffers
    if (tid < 24) {
        int r = tid % 6, arr = (tid / 6) & 1, bufi = tid / 12;
        char* rowp = aptr + bufi * CSTG + arr * SA_L + r * 2112;
        int grow = h0 + r - 1;
        if (grow < 0 || grow >= HH) {
            for (int i = 0; i < 132; i++) ((float4*)rowp)[i] = make_float4(0, 0, 0, 0);
        } else {
            ((float4*)rowp)[0] = make_float4(0, 0, 0, 0);
            ((float4*)rowp)[1] = make_float4(0, 0, 0, 0);
            ((float4*)(rowp + 2080))[0] = make_float4(0, 0, 0, 0);
            ((float4*)(rowp + 2080))[1] = make_float4(0, 0, 0, 0);
        }
    }
    __syncthreads();

    int nvalid = 0;
    for (int r = 0; r < 6; r++) { int g = h0 + r - 1; if (g >= 0 && g < HH) nvalid++; }
    unsigned int txb = 78336u + (unsigned int)nvalid * 4096u;

    auto issue = [&](int s) {
        unsigned int base = abase + (s & 1) * CSTG;
        unsigned int mb = (s & 1) ? mb1 : mb0;
        mbar_expect(mb, txb);
        const bf16* wsrc = wb + ((size_t)(nt * csteps + s) * 2) * 19584;
        bulk_cp(base + SW_H, wsrc, 39168, mb);
        bulk_cp(base + SW_L, wsrc + 19584, 39168, mb);
        for (int r = 0; r < 6; r++) {
            int grow = h0 + r - 1;
            if (grow < 0 || grow >= HH) continue;
            size_t so = ((size_t)(s * BATCH + b) * HH + grow) * WW * 16;
            bulk_cp(base + r * 2112 + 32, inh + so, 2048, mb);
            bulk_cp(base + SA_L + r * 2112 + 32, inl + so, 2048, mb);
        }
    };

    if (tid == 0) { issue(0); if (csteps > 1) issue(1); }
    int ph[2] = {0, 0};

    wmma::fragment<wmma::accumulator, 16, 16, 16, float> acc[2][4];
    #pragma unroll
    for (int mt = 0; mt < 2; mt++)
        #pragma unroll
        for (int nj = 0; nj < 4; nj++) wmma::fill_fragment(acc[mt][nj], 0.f);

    for (int s = 0; s < csteps; s++) {
        int m = s & 1;
        mbar_wait(m ? mb1 : mb0, ph[m]); ph[m] ^= 1;
        char* base = aptr + m * CSTG;
        bf16* Ah = (bf16*)base;
        bf16* Al = (bf16*)(base + SA_L);
        bf16* Wh = (bf16*)(base + SW_H);
        bf16* Wl = (bf16*)(base + SW_L);

        #pragma unroll
        for (int tap = 0; tap < 9; tap++) {
            int ky = tap / 3, kx = tap % 3;
            wmma::fragment<wmma::matrix_a, 16, 16, 16, bf16, wmma::row_major> ah[2], al[2];
            #pragma unroll
            for (int mt = 0; mt < 2; mt++) {
                int t = warpM * 2 + mt;
                int row_l = t >> 2, px0 = (t & 3) * 16;
                int aoff = ((row_l + ky) * 66 + px0 + kx) * 16;
                wmma::load_matrix_sync(ah[mt], Ah + aoff, 16);
                wmma::load_matrix_sync(al[mt], Al + aoff, 16);
            }
            #pragma unroll
            for (int nj = 0; nj < 4; nj++) {
                wmma::fragment<wmma::matrix_b, 16, 16, 16, bf16, wmma::row_major> bh, bl;
                int boff = tap * 2176 + warpN * 64 + nj * 16;
                wmma::load_matrix_sync(bh, Wh + boff, 136);
                wmma::load_matrix_sync(bl, Wl + boff, 136);
                #pragma unroll
                for (int mt = 0; mt < 2; mt++) {
                    wmma::mma_sync(acc[mt][nj], ah[mt], bh, acc[mt][nj]);
                    wmma::mma_sync(acc[mt][nj], ah[mt], bl, acc[mt][nj]);
                    wmma::mma_sync(acc[mt][nj], al[mt], bh, acc[mt][nj]);
                }
            }
        }
        __syncthreads();
        if (tid == 0 && s + 2 < csteps) issue(s + 2);
    }

    // epilogue (reuse smem as per-warp staging)
    float* buf = (float*)aptr + warp * 320;
    #pragma unroll
    for (int mt = 0; mt < 2; mt++) {
        int t = warpM * 2 + mt;
        int row_l = t >> 2, px0 = (t & 3) * 16;
        int grow = h0 + row_l;
        #pragma unroll
        for (int nj = 0; nj < 4; nj++) {
            wmma::store_matrix_sync(buf, acc[mt][nj], 20, wmma::mem_row_major);
            __syncwarp();
            #pragma unroll
            for (int l = 0; l < 8; l++) {
                int e = l * 32 + lane;
                int r = e >> 4, c = e & 15;
                int gn = oc0 + warpN * 64 + nj * 16 + c;
                int pix = (b * HH + grow) * WW + px0 + r;
                float v = buf[r * 20 + c];
                float sc = bng[gn] * rsqrtf(1.f + EPS);
                v = fmaxf(v * sc + bnb[gn], 0.f);
                if (out_f) {
                    out_f[(size_t)pix * CC + gn] = v;
                } else {
                    bf16 hi, lo; split_bf16(v, hi, lo);
                    size_t bo = ((size_t)(gn >> 4) * BHW + pix) * 16 + (gn & 15);
                    obh[bo] = hi; obl[bo] = lo;
                }
            }
            __syncwarp();
        }
    }
}

// ---------------- classifier ----------------
__global__ void k_classifier(const float* __restrict__ drop_w, float* __restrict__ out) {
    __shared__ float Xs[32][65];
    __shared__ float Ws[KK][33];
    int tid = threadIdx.x;
    int row0 = blockIdx.x * 64;
    int b = row0 >> 12, hw0 = row0 & 4095;
    float acc[5] = {0.f, 0.f, 0.f, 0.f, 0.f};
    for (int c0 = 0; c0 < CC; c0 += 32) {
        for (int idx = tid; idx < 2048; idx += 256) {
            int r = idx >> 5, cc = idx & 31;
            Xs[cc][r] = g_x3[(size_t)(row0 + r) * CC + c0 + cc];
        }
        for (int idx = tid; idx < KK * 32; idx += 256) {
            int k = idx >> 5, cc = idx & 31;
            Ws[k][cc] = drop_w[(size_t)k * CC + c0 + cc];
        }
        __syncthreads();
        #pragma unroll
        for (int si = 0; si < 5; si++) {
            int o = tid + si * 256;
            if (o < KK * 64) {
                int k = o >> 6, r = o & 63;
                float a = acc[si];
                #pragma unroll 8
                for (int cc = 0; cc < 32; cc++) a += Ws[k][cc] * Xs[cc][r];
                acc[si] = a;
            }
        }
        __syncthreads();
    }
    #pragma unroll
    for (int si = 0; si < 5; si++) {
        int o = tid + si * 256;
        if (o < KK * 64) {
            int k = o >> 6, r = o & 63;
            out[((size_t)b * KK + k) * HW + hw0 + r] = acc[si];
        }
    }
}

// ---------------- launch ----------------
#define GSA(p, s) cudaGetSymbolAddress((void**)&p, s)
extern "C" void kernel_launch(void* const* d_in, const int* in_sizes, int n_in,
                              void* d_out, int out_size) {
    const float* M_1   = (const float*)d_in[0];
    const float* F     = (const float*)d_in[1];
    const float* I     = (const float*)d_in[2];
    const float* R     = (const float*)d_in[3];
    const float* lg_w1 = (const float*)d_in[4];
    const float* lg_w2 = (const float*)d_in[5];
    const float* fuse_w= (const float*)d_in[6];
    const float* fuse_b= (const float*)d_in[7];
    const float* q_w   = (const float*)d_in[8];
    const float* q_b   = (const float*)d_in[9];
    const float* k_w   = (const float*)d_in[10];
    const float* k_b   = (const float*)d_in[11];
    const float* v_w   = (const float*)d_in[12];
    const float* v_b   = (const float*)d_in[13];
    const float* c1_w  = (const float*)d_in[14];
    const float* bn1_g = (const float*)d_in[15];
    const float* bn1_b = (const float*)d_in[16];
    const float* c2_w  = (const float*)d_in[17];
    const float* bn2_g = (const float*)d_in[18];
    const float* bn2_b = (const float*)d_in[19];
    const float* c3_w  = (const float*)d_in[20];
    const float* bn3_g = (const float*)d_in[21];
    const float* bn3_b = (const float*)d_in[22];
    const float* drop_w= (const float*)d_in[23];
    float* out = (float*)d_out;

    float *p_Fnhwc, *p_Fl2, *p_Fg, *p_q, *p_k, *p_v, *p_x3;
    bf16 *p_Fh, *p_Flo, *p_hh, *p_hl, *p_Fl2h, *p_Fl2l, *p_Fsh, *p_Fsl;
    bf16 *p_Fo1bh, *p_Fo1bl, *p_catbh, *p_catbl, *p_w2b, *p_w3b;
    bf16 *p_qwh, *p_qwl, *p_kwh, *p_kwl, *p_lgwh, *p_lgwl, *p_c1h, *p_c1l;
    GSA(p_Fnhwc, g_Fnhwc); GSA(p_Fl2, g_Fl2); GSA(p_Fg, g_Fg);
    GSA(p_q, g_query); GSA(p_k, g_key); GSA(p_v, g_value); GSA(p_x3, g_x3);
    GSA(p_Fh, g_Fh); GSA(p_Flo, g_Flo); GSA(p_hh, g_hh); GSA(p_hl, g_hl);
    GSA(p_Fl2h, g_Fl2h); GSA(p_Fl2l, g_Fl2l); GSA(p_Fsh, g_Fsh); GSA(p_Fsl, g_Fsl);
    GSA(p_Fo1bh, g_Fo1bh); GSA(p_Fo1bl, g_Fo1bl);
    GSA(p_catbh, g_catbh); GSA(p_catbl, g_catbl);
    GSA(p_w2b, g_w2b); GSA(p_w3b, g_w3b);
    GSA(p_qwh, g_qwh); GSA(p_qwl, g_qwl); GSA(p_kwh, g_kwh); GSA(p_kwl, g_kwl);
    GSA(p_lgwh, g_lgwh); GSA(p_lgwl, g_lgwl); GSA(p_c1h, g_c1h); GSA(p_c1l, g_c1l);

    dim3 blk32(32, 8);
    const int GEMM_SMEM = 2 * GSTAGE_B;
    cudaFuncSetAttribute(k_conv_bulk, cudaFuncAttributeMaxDynamicSharedMemorySize, CONVB_SMEM);
    cudaFuncSetAttribute(k_gemm_mma<0>, cudaFuncAttributeMaxDynamicSharedMemorySize, GEMM_SMEM);
    cudaFuncSetAttribute(k_gemm_mma<1>, cudaFuncAttributeMaxDynamicSharedMemorySize, GEMM_SMEM);
    cudaFuncSetAttribute(k_gemm_mma<2>, cudaFuncAttributeMaxDynamicSharedMemorySize, GEMM_SMEM);

    // weight prep
    k_wprep<<<(4 * 32 * 2 * 19584 + 255) / 256, 256>>>(c2_w, p_w2b, 512, 32);
    k_wprep<<<(int)(((size_t)4 * 160 * 2 * 19584 + 255) / 256), 256>>>(c3_w, p_w3b, 2560, 160);
    k_wtsplit<<<512, 256>>>(q_w, p_qwh, p_qwl, 512, 256);
    k_wtsplit<<<512, 256>>>(k_w, p_kwh, p_kwl, 512, 256);
    k_wtsplit<<<1024, 256>>>(lg_w2, p_lgwh, p_lgwl, 512, 512);
    k_wtsplit<<<512, 256>>>(c1_w, p_c1h, p_c1l, 256, 512);

    // activation prep
    k_transpose_f<<<dim3(HW / 32, CC / 32, BATCH), blk32>>>(F, p_Fnhwc, p_Fh, p_Flo);
    k_transpose_m1<<<dim3(HW / 32, 2048 / 32, BATCH), blk32>>>(M_1, p_catbh, p_catbl);
    k_patch_fl<<<BATCH * PP, 256>>>(I, R);
    k_lg1<<<dim3(CC / 64, BATCH * KK), 256>>>(lg_w1);

    k_gemm_mma<0><<<dim3(4, 19), 512, GEMM_SMEM>>>(
        p_hh, p_hl, p_lgwh, p_lgwl, 512, 512, p_Fl2, p_Fl2h, p_Fl2l,
        nullptr, nullptr, nullptr, nullptr);
    k_fuse<<<BATCH * KK, CC>>>(fuse_w, fuse_b);

    k_gemm_mma<1><<<dim3(2, 64), 512, GEMM_SMEM>>>(
        p_Fh, p_Flo, p_qwh, p_qwl, 512, 256, p_q, nullptr, nullptr,
        q_b, nullptr, nullptr, nullptr);
    k_gemm_mma<1><<<dim3(2, 19), 512, GEMM_SMEM>>>(
        p_Fl2h, p_Fl2l, p_kwh, p_kwl, 512, 256, p_k, nullptr, nullptr,
        k_b, nullptr, nullptr, nullptr);
    k_gemm_v<<<dim3(DD / 64, 2), 256>>>(p_Fg, v_w, p_v, BATCH * KK, DD, CC, v_b);

    k_attn<<<BATCH * PP, 256>>>();

    // Fo1 blocked
    k_gemm_mma<2><<<dim3(4, 64), 512, GEMM_SMEM>>>(
        p_Fsh, p_Fsl, p_c1h, p_c1l, 256, 512, nullptr, p_Fo1bh, p_Fo1bl,
        nullptr, bn1_g, bn1_b, p_Fnhwc);

    // conv2: Fo1 blocked (32 chunks) -> cat blocked chunks 0..31
    k_conv_bulk<<<dim3(BATCH * 16, 4), 512, CONVB_SMEM>>>(
        p_Fo1bh, p_Fo1bl, 32, p_w2b, bn2_g, bn2_b, nullptr, p_catbh, p_catbl);
    // conv3: cat blocked (160 chunks) -> x3 fp32 NHWC
    k_conv_bulk<<<dim3(BATCH * 16, 4), 512, CONVB_SMEM>>>(
        p_catbh, p_catbl, 160, p_w3b, bn3_g, bn3_b, p_x3, nullptr, nullptr);

    k_classifier<<<(BATCH * HW) / 64, 256>>>(drop_w, out);
}

// round 10
// speedup vs baseline: 1.5206x; 1.2405x over previous
#include <cuda_runtime.h>
#include <cuda_fp16.h>
#include <mma.h>
#include <math.h>
#include <stdint.h>

using namespace nvcuda;
typedef __half h16;

#define EPS 1e-5f
#define BATCH 4
#define HH 64
#define WW 64
#define HW 4096
#define BHW 16384
#define CC 512
#define KK 19
#define PP 64
#define NN 64
#define DD 256

__device__ float g_Fnhwc[BATCH * HW * CC];
__device__ float g_Fl[BATCH * PP * KK * CC];
__device__ float g_Fl2[BATCH * PP * KK * CC];
__device__ float g_Fg[BATCH * KK * CC];
__device__ float g_query[BATCH * HW * DD];
__device__ float g_key[BATCH * PP * KK * DD];
__device__ float g_value[BATCH * KK * DD];
__device__ float g_x3[BATCH * HW * CC];

// single-fp16 activations
__device__ h16 g_F16[BATCH * HW * CC];
__device__ h16 g_h16[BATCH * PP * KK * CC];
__device__ h16 g_Fl216[BATCH * PP * KK * CC];
__device__ h16 g_Fs16[BATCH * HW * DD];
// channel-blocked activations: [chunk][B][H][W][16]
__device__ h16 g_Fo1b[32 * BHW * 16];
__device__ h16 g_catb[(size_t)160 * BHW * 16];

// conv weights blocked for bulk copy: [ntile(4)][chunk][term(2)][tap9][k16][136]
__device__ h16 g_w2b[4 * 32 * 2 * 19584];
__device__ h16 g_w3b[(size_t)4 * 160 * 2 * 19584];
// GEMM weight pairs [K][N]
__device__ h16 g_qwh[512 * 256], g_qwl[512 * 256];
__device__ h16 g_kwh[512 * 256], g_kwl[512 * 256];
__device__ h16 g_lgwh[512 * 512], g_lgwl[512 * 512];
__device__ h16 g_c1h[256 * 512], g_c1l[256 * 512];

__device__ __forceinline__ void split_h16(float v, h16& hi, h16& lo) {
    hi = __float2half(v);
    lo = __float2half(v - __half2float(hi));
}
__device__ __forceinline__ void cpa16(void* sdst, const void* gsrc) {
    unsigned int s = (unsigned int)__cvta_generic_to_shared(sdst);
    asm volatile("cp.async.cg.shared.global [%0], [%1], 16;" :: "r"(s), "l"(gsrc));
}
__device__ __forceinline__ void cpa_commit() { asm volatile("cp.async.commit_group;"); }
template <int N>
__device__ __forceinline__ void cpa_wait() { asm volatile("cp.async.wait_group %0;" :: "n"(N)); }

__device__ __forceinline__ void bulk_cp(unsigned int sdst, const void* gsrc,
                                        unsigned int bytes, unsigned int mbar) {
    asm volatile(
        "cp.async.bulk.shared::cta.global.mbarrier::complete_tx::bytes [%0], [%1], %2, [%3];"
        :: "r"(sdst), "l"(gsrc), "r"(bytes), "r"(mbar) : "memory");
}
__device__ __forceinline__ void mbar_init(unsigned int m, unsigned int c) {
    asm volatile("mbarrier.init.shared.b64 [%0], %1;" :: "r"(m), "r"(c) : "memory");
}
__device__ __forceinline__ void mbar_expect(unsigned int m, unsigned int tx) {
    asm volatile("mbarrier.arrive.expect_tx.shared.b64 _, [%0], %1;" :: "r"(m), "r"(tx) : "memory");
}
__device__ __forceinline__ void mbar_wait(unsigned int m, unsigned int par) {
    unsigned int done;
    asm volatile(
        "{\n\t.reg .pred p;\n\t"
        "mbarrier.try_wait.parity.acquire.cta.shared::cta.b64 p, [%1], %2;\n\t"
        "selp.b32 %0, 1, 0, p;\n\t}" : "=r"(done) : "r"(m), "r"(par) : "memory");
    if (!done) {
        asm volatile(
            "{\n\t.reg .pred P1;\n\tWL_%=:\n\t"
            "mbarrier.try_wait.parity.acquire.cta.shared::cta.b64 P1, [%0], %1, 0x989680;\n\t"
            "@P1 bra.uni WD_%=;\n\tbra.uni WL_%=;\n\tWD_%=:\n\t}"
            :: "r"(m), "r"(par) : "memory");
    }
}

// ---------------- transposes ----------------
__global__ void k_transpose_f(const float* __restrict__ in, float* __restrict__ out,
                              h16* __restrict__ o16) {
    __shared__ float tile[32][33];
    int b = blockIdx.z, hw0 = blockIdx.x * 32, c0 = blockIdx.y * 32;
    int tx = threadIdx.x, ty = threadIdx.y;
    for (int i = ty; i < 32; i += 8)
        tile[i][tx] = in[((size_t)b * CC + c0 + i) * HW + hw0 + tx];
    __syncthreads();
    for (int i = ty; i < 32; i += 8) {
        float v = tile[tx][i];
        size_t o = ((size_t)b * HW + hw0 + i) * CC + c0 + tx;
        out[o] = v;
        o16[o] = __float2half(v);
    }
}
__global__ void k_transpose_m1(const float* __restrict__ in, h16* __restrict__ ob) {
    __shared__ float tile[32][33];
    int b = blockIdx.z, hw0 = blockIdx.x * 32, c0 = blockIdx.y * 32;
    int tx = threadIdx.x, ty = threadIdx.y;
    for (int i = ty; i < 32; i += 8)
        tile[i][tx] = in[((size_t)b * 2048 + c0 + i) * HW + hw0 + tx];
    __syncthreads();
    for (int i = ty; i < 32; i += 8) {
        int cg = 512 + c0 + tx;
        size_t o = ((size_t)(cg >> 4) * BHW + (size_t)b * HW + hw0 + i) * 16 + (cg & 15);
        ob[o] = __float2half(tile[tx][i]);
    }
}

// conv weight prep: OIHW -> [ntile][chunk][term][tap9][k16][136]
__global__ void k_wprep(const float* __restrict__ w, h16* __restrict__ dst,
                        int Cin, int csteps) {
    size_t d = (size_t)blockIdx.x * 256 + threadIdx.x;
    size_t total = (size_t)4 * csteps * 2 * 19584;
    if (d >= total) return;
    int oc = d % 136;
    size_t r = d / 136;
    int k = r % 16; r /= 16;
    int tap = r % 9; r /= 9;
    int t = r & 1; r >>= 1;
    int ch = r % csteps;
    int nt = r / csteps;
    h16 outv = __float2half(0.f);
    if (oc < 128) {
        float v = w[((size_t)(nt * 128 + oc) * Cin + ch * 16 + k) * 9 + tap];
        h16 hi, lo; split_h16(v, hi, lo);
        outv = t ? lo : hi;
    }
    dst[d] = outv;
}
__global__ void k_wtsplit(const float* __restrict__ w, h16* __restrict__ oh,
                          h16* __restrict__ ol, int K, int N) {
    int d = blockIdx.x * 256 + threadIdx.x;
    if (d >= K * N) return;
    int k = d / N, n = d % N;
    h16 hi, lo; split_h16(w[(size_t)n * K + k], hi, lo);
    oh[d] = hi; ol[d] = lo;
}

// ---------------- patch softmax + F_l ----------------
__global__ void k_patch_fl(const float* __restrict__ I, const float* __restrict__ R) {
    int bp = blockIdx.x, b = bp >> 6, p = bp & 63;
    int ph = p >> 3, pw = p & 7, tid = threadIdx.x;
    __shared__ float lg[KK][NN];
    __shared__ float pix[NN][20];
    __shared__ float bc[KK];
    __shared__ float Fp[NN][65];
    for (int idx = tid; idx < KK * NN; idx += 256) {
        int k = idx / NN, n = idx % NN;
        int h = ph * 8 + (n >> 3), w = pw * 8 + (n & 7);
        lg[k][n] = I[(((size_t)b * KK + k) * HH + h) * WW + w];
    }
    if (tid < KK) bc[tid] = R[((size_t)b * KK + tid) * PP + p];
    __syncthreads();
    if (tid < KK) {
        float mx = -1e30f;
        for (int n = 0; n < NN; n++) mx = fmaxf(mx, lg[tid][n]);
        float s = 0.f;
        for (int n = 0; n < NN; n++) { float e = __expf(lg[tid][n] - mx); pix[n][tid] = e; s += e; }
        float inv = 1.f / s;
        for (int n = 0; n < NN; n++) pix[n][tid] *= inv;
    }
    __syncthreads();
    for (int c0 = 0; c0 < CC; c0 += 64) {
        for (int idx = tid; idx < NN * 64; idx += 256) {
            int n = idx >> 6, cc = idx & 63;
            int h = ph * 8 + (n >> 3), w = pw * 8 + (n & 7);
            Fp[n][cc] = g_Fnhwc[((size_t)b * HW + h * WW + w) * CC + c0 + cc];
        }
        __syncthreads();
        for (int o = tid; o < KK * 64; o += 256) {
            int k = o >> 6, cc = o & 63;
            float acc = 0.f;
            #pragma unroll 8
            for (int n = 0; n < NN; n++) acc += pix[n][k] * Fp[n][cc];
            g_Fl[((size_t)bp * KK + k) * CC + c0 + cc] = acc * bc[k];
        }
        __syncthreads();
    }
}

__global__ void k_lg1(const float* __restrict__ lg_w1) {
    int c0 = blockIdx.x * 64, bk = blockIdx.y;
    int b = bk / KK, k = bk % KK, tid = threadIdx.x;
    __shared__ float w1[64][64];
    __shared__ float Fl[64][65];
    for (int idx = tid; idx < 4096; idx += 256) w1[idx >> 6][idx & 63] = lg_w1[idx];
    for (int idx = tid; idx < 4096; idx += 256) {
        int p = idx >> 6, cc = idx & 63;
        Fl[p][cc] = g_Fl[(((size_t)b * PP + p) * KK + k) * CC + c0 + cc];
    }
    __syncthreads();
    for (int o = tid; o < 4096; o += 256) {
        int q = o >> 6, cc = o & 63;
        float acc = Fl[q][cc];
        #pragma unroll 8
        for (int p = 0; p < 64; p++) acc += w1[q][p] * Fl[p][cc];
        g_h16[(((size_t)b * PP + q) * KK + k) * CC + c0 + cc] = __float2half(fmaxf(acc, 0.f));
    }
}

__global__ void k_gemm_v(const float* __restrict__ A, const float* __restrict__ Bw,
                         float* __restrict__ C, int M, int N, int K,
                         const float* __restrict__ bias) {
    __shared__ float As[16][68];
    __shared__ float Bs[16][68];
    int m0 = blockIdx.y * 64, n0 = blockIdx.x * 64, tid = threadIdx.x;
    int tx = tid & 15, ty = tid >> 4;
    float acc[4][4] = {};
    for (int k0 = 0; k0 < K; k0 += 16) {
        for (int idx = tid; idx < 1024; idx += 256) {
            int i = idx >> 4, kk = idx & 15;
            int m = m0 + i;
            As[kk][i] = (m < M) ? A[(size_t)m * K + k0 + kk] : 0.f;
        }
        for (int idx = tid; idx < 1024; idx += 256) {
            int j = idx >> 4, kk = idx & 15;
            Bs[kk][j] = Bw[(size_t)(n0 + j) * K + k0 + kk];
        }
        __syncthreads();
        #pragma unroll
        for (int kk = 0; kk < 16; kk++) {
            float a[4], bv[4];
            #pragma unroll
            for (int i = 0; i < 4; i++) a[i] = As[kk][ty * 4 + i];
            #pragma unroll
            for (int j = 0; j < 4; j++) bv[j] = Bs[kk][tx * 4 + j];
            #pragma unroll
            for (int i = 0; i < 4; i++)
                #pragma unroll
                for (int j = 0; j < 4; j++) acc[i][j] += a[i] * bv[j];
        }
        __syncthreads();
    }
    #pragma unroll
    for (int i = 0; i < 4; i++) {
        int m = m0 + ty * 4 + i;
        if (m >= M) continue;
        #pragma unroll
        for (int j = 0; j < 4; j++)
            C[(size_t)m * N + n0 + tx * 4 + j] = acc[i][j] + bias[n0 + tx * 4 + j];
    }
}

__global__ void k_fuse(const float* __restrict__ fw, const float* __restrict__ fb) {
    int bk = blockIdx.x, c = threadIdx.x;
    int b = bk / KK, k = bk % KK;
    float acc = fb[0];
    #pragma unroll 8
    for (int p = 0; p < PP; p++)
        acc += fw[p] * g_Fl2[(((size_t)b * PP + p) * KK + k) * CC + c];
    g_Fg[(size_t)bk * CC + c] = acc;
}

__global__ void k_attn() {
    int bp = blockIdx.x, b = bp >> 6, p = bp & 63;
    int ph = p >> 3, pw = p & 7, tid = threadIdx.x;
    __shared__ float ks[KK][DD];
    __shared__ float vs[KK][DD];
    for (int idx = tid; idx < KK * DD; idx += 256)
        ((float*)ks)[idx] = g_key[(size_t)bp * KK * DD + idx];
    for (int idx = tid; idx < KK * DD; idx += 256)
        ((float*)vs)[idx] = g_value[(size_t)b * KK * DD + idx];
    __syncthreads();
    int warp = tid >> 5, lane = tid & 31;
    for (int n = warp; n < NN; n += 8) {
        int h = ph * 8 + (n >> 3), w = pw * 8 + (n & 7);
        const float* qrow = &g_query[((size_t)b * HW + h * WW + w) * DD];
        float qr[8];
        #pragma unroll
        for (int i = 0; i < 8; i++) qr[i] = qrow[i * 32 + lane];
        float acc[KK];
        #pragma unroll
        for (int k = 0; k < KK; k++) acc[k] = 0.f;
        #pragma unroll
        for (int i = 0; i < 8; i++) {
            float qd = qr[i];
            #pragma unroll
            for (int k = 0; k < KK; k++) acc[k] += qd * ks[k][i * 32 + lane];
        }
        #pragma unroll
        for (int k = 0; k < KK; k++)
            #pragma unroll
            for (int off = 16; off > 0; off >>= 1)
                acc[k] += __shfl_xor_sync(0xFFFFFFFFu, acc[k], off);
        float mx = -1e30f;
        #pragma unroll
        for (int k = 0; k < KK; k++) mx = fmaxf(mx, acc[k]);
        float sum = 0.f;
        #pragma unroll
        for (int k = 0; k < KK; k++) { acc[k] = __expf(acc[k] - mx); sum += acc[k]; }
        float inv = 1.f / sum;
        #pragma unroll
        for (int k = 0; k < KK; k++) acc[k] *= inv;
        size_t ob = ((size_t)b * HW + h * WW + w) * DD;
        #pragma unroll
        for (int i = 0; i < 8; i++) {
            int d = i * 32 + lane;
            float o = 0.f;
            #pragma unroll
            for (int k = 0; k < KK; k++) o += acc[k] * vs[k][d];
            g_Fs16[ob + d] = __float2half(o);
        }
    }
}

// ---------------- 2-term fp16 wmma GEMM: C = A16[M,K] @ (Wh+Wl)[K,N] ----------------
// block 256x128, 512 thr. MODE0: fp32 + fp16 single. MODE1: fp32+bias. MODE2: blocked fp16.
// stage: A 8192B | Wh 4352B | Wl 4352B = 16896B
#define GSTAGE_B 16896
template <int MODE>
__global__ __launch_bounds__(512)
void k_gemm_mma(const h16* __restrict__ Ag, const h16* __restrict__ Wth,
                const h16* __restrict__ Wtl, int K, int N,
                float* __restrict__ Cf, h16* __restrict__ C16,
                const float* __restrict__ bias,
                const float* __restrict__ bng, const float* __restrict__ bnb,
                const float* __restrict__ resid) {
    extern __shared__ char smem[];
    int n0 = blockIdx.x * 128, m0 = blockIdx.y * 256;
    int tid = threadIdx.x, lane = tid & 31, warp = tid >> 5;
    int warpM = warp >> 1, warpN = warp & 1;
    int iters = K >> 4;

    wmma::fragment<wmma::accumulator, 16, 16, 16, float> acc[2][4];
    #pragma unroll
    for (int mt = 0; mt < 2; mt++)
        #pragma unroll
        for (int nj = 0; nj < 4; nj++) wmma::fill_fragment(acc[mt][nj], 0.f);

    auto issue = [&](int it) {
        int k0 = it << 4;
        char* base = smem + (it & 1) * GSTAGE_B;
        h16* As = (h16*)base;
        h16* Wh = (h16*)(base + 8192);
        h16* Wl = (h16*)(base + 12544);
        {   // A: 256x16 = 512 uint4, one per thread
            int flat = tid * 8;
            int r = flat >> 4, c8 = flat & 15;
            cpa16(As + flat, Ag + (size_t)(m0 + r) * K + k0 + c8);
        }
        {   // W pair: 2 x 256 uint4 over threads (tid<512)
            int u = tid;
            int v = (u < 256) ? u : u - 256;
            int flat = v * 8;
            int kk = flat >> 7, n8 = flat & 127;
            const h16* src = (u < 256) ? Wth : Wtl;
            cpa16(((u < 256) ? Wh : Wl) + kk * 136 + n8,
                  src + (size_t)(k0 + kk) * N + n0 + n8);
        }
        cpa_commit();
    };

    issue(0);
    for (int it = 0; it < iters; it++) {
        cpa_wait<0>();
        __syncthreads();
        if (it + 1 < iters) issue(it + 1);
        char* base = smem + (it & 1) * GSTAGE_B;
        h16* As = (h16*)base;
        h16* Wh = (h16*)(base + 8192);
        h16* Wl = (h16*)(base + 12544);
        #pragma unroll
        for (int mt = 0; mt < 2; mt++) {
            int t = warpM * 2 + mt;
            wmma::fragment<wmma::matrix_a, 16, 16, 16, h16, wmma::row_major> af;
            wmma::load_matrix_sync(af, As + t * 256, 16);
            #pragma unroll
            for (int nj = 0; nj < 4; nj++) {
                wmma::fragment<wmma::matrix_b, 16, 16, 16, h16, wmma::row_major> bh, bl;
                int boff = warpN * 64 + nj * 16;
                wmma::load_matrix_sync(bh, Wh + boff, 136);
                wmma::load_matrix_sync(bl, Wl + boff, 136);
                wmma::mma_sync(acc[mt][nj], af, bh, acc[mt][nj]);
                wmma::mma_sync(acc[mt][nj], af, bl, acc[mt][nj]);
            }
        }
        __syncthreads();
    }

    float* buf = (float*)smem + warp * 320;
    #pragma unroll
    for (int mt = 0; mt < 2; mt++) {
        int t = warpM * 2 + mt;
        #pragma unroll
        for (int nj = 0; nj < 4; nj++) {
            wmma::store_matrix_sync(buf, acc[mt][nj], 20, wmma::mem_row_major);
            __syncwarp();
            #pragma unroll
            for (int l = 0; l < 8; l++) {
                int e = l * 32 + lane;
                int r = e >> 4, c = e & 15;
                int gm = m0 + t * 16 + r;
                int gn = n0 + warpN * 64 + nj * 16 + c;
                float v = buf[r * 20 + c];
                size_t o = (size_t)gm * N + gn;
                if (MODE == 0) {
                    Cf[o] = v;
                    C16[o] = __float2half(v);
                } else if (MODE == 1) {
                    Cf[o] = v + bias[gn];
                } else {
                    float s = bng[gn] * rsqrtf(1.f + EPS);
                    v = resid[o] + fmaxf(v * s + bnb[gn], 0.f);
                    C16[((size_t)(gn >> 4) * BHW + gm) * 16 + (gn & 15)] = __float2half(v);
                }
            }
            __syncwarp();
        }
    }
}

// ---------------- bulk-copy 2-term fp16 3x3 conv ----------------
// block: 256px x 128oc; 512 thr. stage: A[6][66][16]=12672 | Wh 39168 | Wl 39168 = 91008
#define SW_H 12672
#define SW_L 51840
#define CSTG 91008
#define CONVB_SMEM (2 * CSTG + 64)
__global__ __launch_bounds__(512, 1)
void k_conv_bulk(const h16* __restrict__ inb, int csteps, const h16* __restrict__ wb,
                 const float* __restrict__ bng, const float* __restrict__ bnb,
                 float* __restrict__ out_f, h16* __restrict__ ob) {
    extern __shared__ char dsm[];
    char* aptr = (char*)(((size_t)dsm + 127) & ~(size_t)127);
    unsigned int abase = (unsigned int)__cvta_generic_to_shared(aptr);
    unsigned int mb0 = abase + 2 * CSTG, mb1 = mb0 + 8;

    int tid = threadIdx.x, lane = tid & 31, warp = tid >> 5;
    int warpM = warp >> 1, warpN = warp & 1;
    int b = blockIdx.x >> 4, h0 = (blockIdx.x & 15) << 2;
    int nt = blockIdx.y;
    int oc0 = nt << 7;

    if (tid == 0) { mbar_init(mb0, 1); mbar_init(mb1, 1); }
    // zero-once halos (both buffers)
    if (tid < 12) {
        int r = tid % 6, bufi = tid / 6;
        char* rowp = aptr + bufi * CSTG + r * 2112;
        int grow = h0 + r - 1;
        if (grow < 0 || grow >= HH) {
            for (int i = 0; i < 132; i++) ((float4*)rowp)[i] = make_float4(0, 0, 0, 0);
        } else {
            ((float4*)rowp)[0] = make_float4(0, 0, 0, 0);
            ((float4*)rowp)[1] = make_float4(0, 0, 0, 0);
            ((float4*)(rowp + 2080))[0] = make_float4(0, 0, 0, 0);
            ((float4*)(rowp + 2080))[1] = make_float4(0, 0, 0, 0);
        }
    }
    __syncthreads();

    int nvalid = 0;
    for (int r = 0; r < 6; r++) { int g = h0 + r - 1; if (g >= 0 && g < HH) nvalid++; }
    unsigned int txb = 78336u + (unsigned int)nvalid * 2048u;

    auto issue = [&](int s) {
        unsigned int base = abase + (s & 1) * CSTG;
        unsigned int mb = (s & 1) ? mb1 : mb0;
        mbar_expect(mb, txb);
        const h16* wsrc = wb + ((size_t)(nt * csteps + s) * 2) * 19584;
        bulk_cp(base + SW_H, wsrc, 39168, mb);
        bulk_cp(base + SW_L, wsrc + 19584, 39168, mb);
        for (int r = 0; r < 6; r++) {
            int grow = h0 + r - 1;
            if (grow < 0 || grow >= HH) continue;
            size_t so = ((size_t)(s * BATCH + b) * HH + grow) * WW * 16;
            bulk_cp(base + r * 2112 + 32, inb + so, 2048, mb);
        }
    };

    if (tid == 0) { issue(0); if (csteps > 1) issue(1); }
    int ph[2] = {0, 0};

    wmma::fragment<wmma::accumulator, 16, 16, 16, float> acc[2][4];
    #pragma unroll
    for (int mt = 0; mt < 2; mt++)
        #pragma unroll
        for (int nj = 0; nj < 4; nj++) wmma::fill_fragment(acc[mt][nj], 0.f);

    for (int s = 0; s < csteps; s++) {
        int m = s & 1;
        mbar_wait(m ? mb1 : mb0, ph[m]); ph[m] ^= 1;
        char* base = aptr + m * CSTG;
        h16* As = (h16*)base;
        h16* Wh = (h16*)(base + SW_H);
        h16* Wl = (h16*)(base + SW_L);

        #pragma unroll
        for (int tap = 0; tap < 9; tap++) {
            int ky = tap / 3, kx = tap % 3;
            wmma::fragment<wmma::matrix_a, 16, 16, 16, h16, wmma::row_major> af[2];
            #pragma unroll
            for (int mt = 0; mt < 2; mt++) {
                int t = warpM * 2 + mt;
                int row_l = t >> 2, px0 = (t & 3) * 16;
                wmma::load_matrix_sync(af[mt], As + ((row_l + ky) * 66 + px0 + kx) * 16, 16);
            }
            #pragma unroll
            for (int nj = 0; nj < 4; nj++) {
                wmma::fragment<wmma::matrix_b, 16, 16, 16, h16, wmma::row_major> bh, bl;
                int boff = tap * 2176 + warpN * 64 + nj * 16;
                wmma::load_matrix_sync(bh, Wh + boff, 136);
                wmma::load_matrix_sync(bl, Wl + boff, 136);
                #pragma unroll
                for (int mt = 0; mt < 2; mt++) {
                    wmma::mma_sync(acc[mt][nj], af[mt], bh, acc[mt][nj]);
                    wmma::mma_sync(acc[mt][nj], af[mt], bl, acc[mt][nj]);
                }
            }
        }
        __syncthreads();
        if (tid == 0 && s + 2 < csteps) issue(s + 2);
    }

    float* buf = (float*)aptr + warp * 320;
    #pragma unroll
    for (int mt = 0; mt < 2; mt++) {
        int t = warpM * 2 + mt;
        int row_l = t >> 2, px0 = (t & 3) * 16;
        int grow = h0 + row_l;
        #pragma unroll
        for (int nj = 0; nj < 4; nj++) {
            wmma::store_matrix_sync(buf, acc[mt][nj], 20, wmma::mem_row_major);
            __syncwarp();
            #pragma unroll
            for (int l = 0; l < 8; l++) {
                int e = l * 32 + lane;
                int r = e >> 4, c = e & 15;
                int gn = oc0 + warpN * 64 + nj * 16 + c;
                int pix = (b * HH + grow) * WW + px0 + r;
                float v = buf[r * 20 + c];
                float sc = bng[gn] * rsqrtf(1.f + EPS);
                v = fmaxf(v * sc + bnb[gn], 0.f);
                if (out_f) out_f[(size_t)pix * CC + gn] = v;
                else ob[((size_t)(gn >> 4) * BHW + pix) * 16 + (gn & 15)] = __float2half(v);
            }
            __syncwarp();
        }
    }
}

// ---------------- classifier ----------------
__global__ void k_classifier(const float* __restrict__ drop_w, float* __restrict__ out) {
    __shared__ float Xs[32][65];
    __shared__ float Ws[KK][33];
    int tid = threadIdx.x;
    int row0 = blockIdx.x * 64;
    int b = row0 >> 12, hw0 = row0 & 4095;
    float acc[5] = {0.f, 0.f, 0.f, 0.f, 0.f};
    for (int c0 = 0; c0 < CC; c0 += 32) {
        for (int idx = tid; idx < 2048; idx += 256) {
            int r = idx >> 5, cc = idx & 31;
            Xs[cc][r] = g_x3[(size_t)(row0 + r) * CC + c0 + cc];
        }
        for (int idx = tid; idx < KK * 32; idx += 256) {
            int k = idx >> 5, cc = idx & 31;
            Ws[k][cc] = drop_w[(size_t)k * CC + c0 + cc];
        }
        __syncthreads();
        #pragma unroll
        for (int si = 0; si < 5; si++) {
            int o = tid + si * 256;
            if (o < KK * 64) {
                int k = o >> 6, r = o & 63;
                float a = acc[si];
                #pragma unroll 8
                for (int cc = 0; cc < 32; cc++) a += Ws[k][cc] * Xs[cc][r];
                acc[si] = a;
            }
        }
        __syncthreads();
    }
    #pragma unroll
    for (int si = 0; si < 5; si++) {
        int o = tid + si * 256;
        if (o < KK * 64) {
            int k = o >> 6, r = o & 63;
            out[((size_t)b * KK + k) * HW + hw0 + r] = acc[si];
        }
    }
}

// ---------------- launch ----------------
#define GSA(p, s) cudaGetSymbolAddress((void**)&p, s)
extern "C" void kernel_launch(void* const* d_in, const int* in_sizes, int n_in,
                              void* d_out, int out_size) {
    const float* M_1   = (const float*)d_in[0];
    const float* F     = (const float*)d_in[1];
    const float* I     = (const float*)d_in[2];
    const float* R     = (const float*)d_in[3];
    const float* lg_w1 = (const float*)d_in[4];
    const float* lg_w2 = (const float*)d_in[5];
    const float* fuse_w= (const float*)d_in[6];
    const float* fuse_b= (const float*)d_in[7];
    const float* q_w   = (const float*)d_in[8];
    const float* q_b   = (const float*)d_in[9];
    const float* k_w   = (const float*)d_in[10];
    const float* k_b   = (const float*)d_in[11];
    const float* v_w   = (const float*)d_in[12];
    const float* v_b   = (const float*)d_in[13];
    const float* c1_w  = (const float*)d_in[14];
    const float* bn1_g = (const float*)d_in[15];
    const float* bn1_b = (const float*)d_in[16];
    const float* c2_w  = (const float*)d_in[17];
    const float* bn2_g = (const float*)d_in[18];
    const float* bn2_b = (const float*)d_in[19];
    const float* c3_w  = (const float*)d_in[20];
    const float* bn3_g = (const float*)d_in[21];
    const float* bn3_b = (const float*)d_in[22];
    const float* drop_w= (const float*)d_in[23];
    float* out = (float*)d_out;

    float *p_Fnhwc, *p_Fl2, *p_Fg, *p_q, *p_k, *p_v, *p_x3;
    h16 *p_F16, *p_h16, *p_Fl216, *p_Fs16, *p_Fo1b, *p_catb, *p_w2b, *p_w3b;
    h16 *p_qwh, *p_qwl, *p_kwh, *p_kwl, *p_lgwh, *p_lgwl, *p_c1h, *p_c1l;
    GSA(p_Fnhwc, g_Fnhwc); GSA(p_Fl2, g_Fl2); GSA(p_Fg, g_Fg);
    GSA(p_q, g_query); GSA(p_k, g_key); GSA(p_v, g_value); GSA(p_x3, g_x3);
    GSA(p_F16, g_F16); GSA(p_h16, g_h16); GSA(p_Fl216, g_Fl216); GSA(p_Fs16, g_Fs16);
    GSA(p_Fo1b, g_Fo1b); GSA(p_catb, g_catb);
    GSA(p_w2b, g_w2b); GSA(p_w3b, g_w3b);
    GSA(p_qwh, g_qwh); GSA(p_qwl, g_qwl); GSA(p_kwh, g_kwh); GSA(p_kwl, g_kwl);
    GSA(p_lgwh, g_lgwh); GSA(p_lgwl, g_lgwl); GSA(p_c1h, g_c1h); GSA(p_c1l, g_c1l);

    dim3 blk32(32, 8);
    const int GEMM_SMEM = 2 * GSTAGE_B;
    cudaFuncSetAttribute(k_conv_bulk, cudaFuncAttributeMaxDynamicSharedMemorySize, CONVB_SMEM);
    cudaFuncSetAttribute(k_gemm_mma<0>, cudaFuncAttributeMaxDynamicSharedMemorySize, GEMM_SMEM);
    cudaFuncSetAttribute(k_gemm_mma<1>, cudaFuncAttributeMaxDynamicSharedMemorySize, GEMM_SMEM);
    cudaFuncSetAttribute(k_gemm_mma<2>, cudaFuncAttributeMaxDynamicSharedMemorySize, GEMM_SMEM);

    k_wprep<<<(4 * 32 * 2 * 19584 + 255) / 256, 256>>>(c2_w, p_w2b, 512, 32);
    k_wprep<<<(int)(((size_t)4 * 160 * 2 * 19584 + 255) / 256), 256>>>(c3_w, p_w3b, 2560, 160);
    k_wtsplit<<<512, 256>>>(q_w, p_qwh, p_qwl, 512, 256);
    k_wtsplit<<<512, 256>>>(k_w, p_kwh, p_kwl, 512, 256);
    k_wtsplit<<<1024, 256>>>(lg_w2, p_lgwh, p_lgwl, 512, 512);
    k_wtsplit<<<512, 256>>>(c1_w, p_c1h, p_c1l, 256, 512);

    k_transpose_f<<<dim3(HW / 32, CC / 32, BATCH), blk32>>>(F, p_Fnhwc, p_F16);
    k_transpose_m1<<<dim3(HW / 32, 2048 / 32, BATCH), blk32>>>(M_1, p_catb);
    k_patch_fl<<<BATCH * PP, 256>>>(I, R);
    k_lg1<<<dim3(CC / 64, BATCH * KK), 256>>>(lg_w1);

    // Fl2 = h @ lg_w2^T
    k_gemm_mma<0><<<dim3(4, 19), 512, GEMM_SMEM>>>(
        p_h16, p_lgwh, p_lgwl, 512, 512, p_Fl2, p_Fl216, nullptr, nullptr, nullptr, nullptr);
    k_fuse<<<BATCH * KK, CC>>>(fuse_w, fuse_b);

    k_gemm_mma<1><<<dim3(2, 64), 512, GEMM_SMEM>>>(
        p_F16, p_qwh, p_qwl, 512, 256, p_q, nullptr, q_b, nullptr, nullptr, nullptr);
    k_gemm_mma<1><<<dim3(2, 19), 512, GEMM_SMEM>>>(
        p_Fl216, p_kwh, p_kwl, 512, 256, p_k, nullptr, k_b, nullptr, nullptr, nullptr);
    k_gemm_v<<<dim3(DD / 64, 2), 256>>>(p_Fg, v_w, p_v, BATCH * KK, DD, CC, v_b);

    k_attn<<<BATCH * PP, 256>>>();

    // Fo1 = F + relu(bn1(F_s @ c1^T)) -> blocked fp16
    k_gemm_mma<2><<<dim3(4, 64), 512, GEMM_SMEM>>>(
        p_Fs16, p_c1h, p_c1l, 256, 512, nullptr, p_Fo1b, nullptr, bn1_g, bn1_b, p_Fnhwc);

    k_conv_bulk<<<dim3(BATCH * 16, 4), 512, CONVB_SMEM>>>(
        p_Fo1b, 32, p_w2b, bn2_g, bn2_b, nullptr, p_catb);
    k_conv_bulk<<<dim3(BATCH * 16, 4), 512, CONVB_SMEM>>>(
        p_catb, 160, p_w3b, bn3_g, bn3_b, p_x3, nullptr);

    k_classifier<<<(BATCH * HW) / 64, 256>>>(drop_w, out);
}

// round 11
// speedup vs baseline: 2.4236x; 1.5939x over previous
#include <cuda_runtime.h>
#include <cuda_fp16.h>
#include <mma.h>
#include <math.h>
#include <stdint.h>

using namespace nvcuda;
typedef __half h16;

#define EPS 1e-5f
#define BATCH 4
#define HH 64
#define WW 64
#define HW 4096
#define BHW 16384
#define CC 512
#define KK 19
#define PP 64
#define NN 64
#define DD 256

__device__ float g_Fnhwc[BATCH * HW * CC];
__device__ float g_Fl[BATCH * PP * KK * CC];
__device__ float g_Fl2[BATCH * PP * KK * CC];
__device__ float g_Fg[BATCH * KK * CC];
__device__ float g_query[BATCH * HW * DD];
__device__ float g_key[BATCH * PP * KK * DD];
__device__ float g_value[BATCH * KK * DD];
__device__ float g_x3[BATCH * HW * CC];

// single-fp16 activations
__device__ h16 g_F16[BATCH * HW * CC];
__device__ h16 g_h16[BATCH * PP * KK * CC];
__device__ h16 g_Fl216[BATCH * PP * KK * CC];
__device__ h16 g_Fs16[BATCH * HW * DD];
// channel-blocked activations: [chunk][B][H][W][16]
__device__ h16 g_Fo1b[32 * BHW * 16];
__device__ h16 g_catb[(size_t)160 * BHW * 16];

// conv weights blocked for bulk copy: [ntile(4)][chunk][tap9][k16][136]
__device__ h16 g_w2b[4 * 32 * 19584];
__device__ h16 g_w3b[(size_t)4 * 160 * 19584];
// GEMM weights [K][N], single fp16
__device__ h16 g_qw16[512 * 256];
__device__ h16 g_kw16[512 * 256];
__device__ h16 g_lgw16[512 * 512];
__device__ h16 g_c116[256 * 512];

__device__ __forceinline__ void cpa16(void* sdst, const void* gsrc) {
    unsigned int s = (unsigned int)__cvta_generic_to_shared(sdst);
    asm volatile("cp.async.cg.shared.global [%0], [%1], 16;" :: "r"(s), "l"(gsrc));
}
__device__ __forceinline__ void cpa_commit() { asm volatile("cp.async.commit_group;"); }
template <int N>
__device__ __forceinline__ void cpa_wait() { asm volatile("cp.async.wait_group %0;" :: "n"(N)); }

__device__ __forceinline__ void bulk_cp(unsigned int sdst, const void* gsrc,
                                        unsigned int bytes, unsigned int mbar) {
    asm volatile(
        "cp.async.bulk.shared::cta.global.mbarrier::complete_tx::bytes [%0], [%1], %2, [%3];"
        :: "r"(sdst), "l"(gsrc), "r"(bytes), "r"(mbar) : "memory");
}
__device__ __forceinline__ void mbar_init(unsigned int m, unsigned int c) {
    asm volatile("mbarrier.init.shared.b64 [%0], %1;" :: "r"(m), "r"(c) : "memory");
}
__device__ __forceinline__ void mbar_expect(unsigned int m, unsigned int tx) {
    asm volatile("mbarrier.arrive.expect_tx.shared.b64 _, [%0], %1;" :: "r"(m), "r"(tx) : "memory");
}
__device__ __forceinline__ void mbar_wait(unsigned int m, unsigned int par) {
    unsigned int done;
    asm volatile(
        "{\n\t.reg .pred p;\n\t"
        "mbarrier.try_wait.parity.acquire.cta.shared::cta.b64 p, [%1], %2;\n\t"
        "selp.b32 %0, 1, 0, p;\n\t}" : "=r"(done) : "r"(m), "r"(par) : "memory");
    if (!done) {
        asm volatile(
            "{\n\t.reg .pred P1;\n\tWL_%=:\n\t"
            "mbarrier.try_wait.parity.acquire.cta.shared::cta.b64 P1, [%0], %1, 0x989680;\n\t"
            "@P1 bra.uni WD_%=;\n\tbra.uni WL_%=;\n\tWD_%=:\n\t}"
            :: "r"(m), "r"(par) : "memory");
    }
}

// ---------------- transposes ----------------
__global__ void k_transpose_f(const float* __restrict__ in, float* __restrict__ out,
                              h16* __restrict__ o16) {
    __shared__ float tile[32][33];
    int b = blockIdx.z, hw0 = blockIdx.x * 32, c0 = blockIdx.y * 32;
    int tx = threadIdx.x, ty = threadIdx.y;
    for (int i = ty; i < 32; i += 8)
        tile[i][tx] = in[((size_t)b * CC + c0 + i) * HW + hw0 + tx];
    __syncthreads();
    for (int i = ty; i < 32; i += 8) {
        float v = tile[tx][i];
        size_t o = ((size_t)b * HW + hw0 + i) * CC + c0 + tx;
        out[o] = v;
        o16[o] = __float2half(v);
    }
}
__global__ void k_transpose_m1(const float* __restrict__ in, h16* __restrict__ ob) {
    __shared__ float tile[32][33];
    int b = blockIdx.z, hw0 = blockIdx.x * 32, c0 = blockIdx.y * 32;
    int tx = threadIdx.x, ty = threadIdx.y;
    for (int i = ty; i < 32; i += 8)
        tile[i][tx] = in[((size_t)b * 2048 + c0 + i) * HW + hw0 + tx];
    __syncthreads();
    for (int i = ty; i < 32; i += 8) {
        int cg = 512 + c0 + tx;
        size_t o = ((size_t)(cg >> 4) * BHW + (size_t)b * HW + hw0 + i) * 16 + (cg & 15);
        ob[o] = __float2half(tile[tx][i]);
    }
}

// conv weight prep: OIHW -> [ntile][chunk][tap9][k16][136]
__global__ void k_wprep(const float* __restrict__ w, h16* __restrict__ dst,
                        int Cin, int csteps) {
    size_t d = (size_t)blockIdx.x * 256 + threadIdx.x;
    size_t total = (size_t)4 * csteps * 19584;
    if (d >= total) return;
    int oc = d % 136;
    size_t r = d / 136;
    int k = r % 16; r /= 16;
    int tap = r % 9; r /= 9;
    int ch = r % csteps;
    int nt = r / csteps;
    h16 outv = __float2half(0.f);
    if (oc < 128)
        outv = __float2half(w[((size_t)(nt * 128 + oc) * Cin + ch * 16 + k) * 9 + tap]);
    dst[d] = outv;
}
__global__ void k_wt16(const float* __restrict__ w, h16* __restrict__ o16, int K, int N) {
    int d = blockIdx.x * 256 + threadIdx.x;
    if (d >= K * N) return;
    int k = d / N, n = d % N;
    o16[d] = __float2half(w[(size_t)n * K + k]);
}

// ---------------- patch softmax + F_l ----------------
__global__ void k_patch_fl(const float* __restrict__ I, const float* __restrict__ R) {
    int bp = blockIdx.x, b = bp >> 6, p = bp & 63;
    int ph = p >> 3, pw = p & 7, tid = threadIdx.x;
    __shared__ float lg[KK][NN];
    __shared__ float pix[NN][20];
    __shared__ float bc[KK];
    __shared__ float Fp[NN][65];
    for (int idx = tid; idx < KK * NN; idx += 256) {
        int k = idx / NN, n = idx % NN;
        int h = ph * 8 + (n >> 3), w = pw * 8 + (n & 7);
        lg[k][n] = I[(((size_t)b * KK + k) * HH + h) * WW + w];
    }
    if (tid < KK) bc[tid] = R[((size_t)b * KK + tid) * PP + p];
    __syncthreads();
    if (tid < KK) {
        float mx = -1e30f;
        for (int n = 0; n < NN; n++) mx = fmaxf(mx, lg[tid][n]);
        float s = 0.f;
        for (int n = 0; n < NN; n++) { float e = __expf(lg[tid][n] - mx); pix[n][tid] = e; s += e; }
        float inv = 1.f / s;
        for (int n = 0; n < NN; n++) pix[n][tid] *= inv;
    }
    __syncthreads();
    for (int c0 = 0; c0 < CC; c0 += 64) {
        for (int idx = tid; idx < NN * 64; idx += 256) {
            int n = idx >> 6, cc = idx & 63;
            int h = ph * 8 + (n >> 3), w = pw * 8 + (n & 7);
            Fp[n][cc] = g_Fnhwc[((size_t)b * HW + h * WW + w) * CC + c0 + cc];
        }
        __syncthreads();
        for (int o = tid; o < KK * 64; o += 256) {
            int k = o >> 6, cc = o & 63;
            float acc = 0.f;
            #pragma unroll 8
            for (int n = 0; n < NN; n++) acc += pix[n][k] * Fp[n][cc];
            g_Fl[((size_t)bp * KK + k) * CC + c0 + cc] = acc * bc[k];
        }
        __syncthreads();
    }
}

__global__ void k_lg1(const float* __restrict__ lg_w1) {
    int c0 = blockIdx.x * 64, bk = blockIdx.y;
    int b = bk / KK, k = bk % KK, tid = threadIdx.x;
    __shared__ float w1[64][64];
    __shared__ float Fl[64][65];
    for (int idx = tid; idx < 4096; idx += 256) w1[idx >> 6][idx & 63] = lg_w1[idx];
    for (int idx = tid; idx < 4096; idx += 256) {
        int p = idx >> 6, cc = idx & 63;
        Fl[p][cc] = g_Fl[(((size_t)b * PP + p) * KK + k) * CC + c0 + cc];
    }
    __syncthreads();
    for (int o = tid; o < 4096; o += 256) {
        int q = o >> 6, cc = o & 63;
        float acc = Fl[q][cc];
        #pragma unroll 8
        for (int p = 0; p < 64; p++) acc += w1[q][p] * Fl[p][cc];
        g_h16[(((size_t)b * PP + q) * KK + k) * CC + c0 + cc] = __float2half(fmaxf(acc, 0.f));
    }
}

__global__ void k_gemm_v(const float* __restrict__ A, const float* __restrict__ Bw,
                         float* __restrict__ C, int M, int N, int K,
                         const float* __restrict__ bias) {
    __shared__ float As[16][68];
    __shared__ float Bs[16][68];
    int m0 = blockIdx.y * 64, n0 = blockIdx.x * 64, tid = threadIdx.x;
    int tx = tid & 15, ty = tid >> 4;
    float acc[4][4] = {};
    for (int k0 = 0; k0 < K; k0 += 16) {
        for (int idx = tid; idx < 1024; idx += 256) {
            int i = idx >> 4, kk = idx & 15;
            int m = m0 + i;
            As[kk][i] = (m < M) ? A[(size_t)m * K + k0 + kk] : 0.f;
        }
        for (int idx = tid; idx < 1024; idx += 256) {
            int j = idx >> 4, kk = idx & 15;
            Bs[kk][j] = Bw[(size_t)(n0 + j) * K + k0 + kk];
        }
        __syncthreads();
        #pragma unroll
        for (int kk = 0; kk < 16; kk++) {
            float a[4], bv[4];
            #pragma unroll
            for (int i = 0; i < 4; i++) a[i] = As[kk][ty * 4 + i];
            #pragma unroll
            for (int j = 0; j < 4; j++) bv[j] = Bs[kk][tx * 4 + j];
            #pragma unroll
            for (int i = 0; i < 4; i++)
                #pragma unroll
                for (int j = 0; j < 4; j++) acc[i][j] += a[i] * bv[j];
        }
        __syncthreads();
    }
    #pragma unroll
    for (int i = 0; i < 4; i++) {
        int m = m0 + ty * 4 + i;
        if (m >= M) continue;
        #pragma unroll
        for (int j = 0; j < 4; j++)
            C[(size_t)m * N + n0 + tx * 4 + j] = acc[i][j] + bias[n0 + tx * 4 + j];
    }
}

__global__ void k_fuse(const float* __restrict__ fw, const float* __restrict__ fb) {
    int bk = blockIdx.x, c = threadIdx.x;
    int b = bk / KK, k = bk % KK;
    float acc = fb[0];
    #pragma unroll 8
    for (int p = 0; p < PP; p++)
        acc += fw[p] * g_Fl2[(((size_t)b * PP + p) * KK + k) * CC + c];
    g_Fg[(size_t)bk * CC + c] = acc;
}

__global__ void k_attn() {
    int bp = blockIdx.x, b = bp >> 6, p = bp & 63;
    int ph = p >> 3, pw = p & 7, tid = threadIdx.x;
    __shared__ float ks[KK][DD];
    __shared__ float vs[KK][DD];
    for (int idx = tid; idx < KK * DD; idx += 256)
        ((float*)ks)[idx] = g_key[(size_t)bp * KK * DD + idx];
    for (int idx = tid; idx < KK * DD; idx += 256)
        ((float*)vs)[idx] = g_value[(size_t)b * KK * DD + idx];
    __syncthreads();
    int warp = tid >> 5, lane = tid & 31;
    for (int n = warp; n < NN; n += 8) {
        int h = ph * 8 + (n >> 3), w = pw * 8 + (n & 7);
        const float* qrow = &g_query[((size_t)b * HW + h * WW + w) * DD];
        float qr[8];
        #pragma unroll
        for (int i = 0; i < 8; i++) qr[i] = qrow[i * 32 + lane];
        float acc[KK];
        #pragma unroll
        for (int k = 0; k < KK; k++) acc[k] = 0.f;
        #pragma unroll
        for (int i = 0; i < 8; i++) {
            float qd = qr[i];
            #pragma unroll
            for (int k = 0; k < KK; k++) acc[k] += qd * ks[k][i * 32 + lane];
        }
        #pragma unroll
        for (int k = 0; k < KK; k++)
            #pragma unroll
            for (int off = 16; off > 0; off >>= 1)
                acc[k] += __shfl_xor_sync(0xFFFFFFFFu, acc[k], off);
        float mx = -1e30f;
        #pragma unroll
        for (int k = 0; k < KK; k++) mx = fmaxf(mx, acc[k]);
        float sum = 0.f;
        #pragma unroll
        for (int k = 0; k < KK; k++) { acc[k] = __expf(acc[k] - mx); sum += acc[k]; }
        float inv = 1.f / sum;
        #pragma unroll
        for (int k = 0; k < KK; k++) acc[k] *= inv;
        size_t ob = ((size_t)b * HW + h * WW + w) * DD;
        #pragma unroll
        for (int i = 0; i < 8; i++) {
            int d = i * 32 + lane;
            float o = 0.f;
            #pragma unroll
            for (int k = 0; k < KK; k++) o += acc[k] * vs[k][d];
            g_Fs16[ob + d] = __float2half(o);
        }
    }
}

// ---------------- 1-term fp16 wmma GEMM: C = A16[M,K] @ W16[K,N] ----------------
// block 256x128, 512 thr. stage: A 8192B | W 4352B = 12544B
#define GSTAGE_B 12544
template <int MODE>
__global__ __launch_bounds__(512)
void k_gemm_mma(const h16* __restrict__ Ag, const h16* __restrict__ Wt,
                int K, int N,
                float* __restrict__ Cf, h16* __restrict__ C16,
                const float* __restrict__ bias,
                const float* __restrict__ bng, const float* __restrict__ bnb,
                const float* __restrict__ resid) {
    extern __shared__ char smem[];
    int n0 = blockIdx.x * 128, m0 = blockIdx.y * 256;
    int tid = threadIdx.x, lane = tid & 31, warp = tid >> 5;
    int warpM = warp >> 1, warpN = warp & 1;
    int iters = K >> 4;

    wmma::fragment<wmma::accumulator, 16, 16, 16, float> acc[2][4];
    #pragma unroll
    for (int mt = 0; mt < 2; mt++)
        #pragma unroll
        for (int nj = 0; nj < 4; nj++) wmma::fill_fragment(acc[mt][nj], 0.f);

    auto issue = [&](int it) {
        int k0 = it << 4;
        char* base = smem + (it & 1) * GSTAGE_B;
        h16* As = (h16*)base;
        h16* Ws = (h16*)(base + 8192);
        {   // A: 256x16 = 512 uint4, one per thread
            int flat = tid * 8;
            int r = flat >> 4, c8 = flat & 15;
            cpa16(As + flat, Ag + (size_t)(m0 + r) * K + k0 + c8);
        }
        if (tid < 256) {   // W: 16x128 = 256 uint4
            int flat = tid * 8;
            int kk = flat >> 7, n8 = flat & 127;
            cpa16(Ws + kk * 136 + n8, Wt + (size_t)(k0 + kk) * N + n0 + n8);
        }
        cpa_commit();
    };

    issue(0);
    for (int it = 0; it < iters; it++) {
        cpa_wait<0>();
        __syncthreads();
        if (it + 1 < iters) issue(it + 1);
        char* base = smem + (it & 1) * GSTAGE_B;
        h16* As = (h16*)base;
        h16* Ws = (h16*)(base + 8192);
        #pragma unroll
        for (int mt = 0; mt < 2; mt++) {
            int t = warpM * 2 + mt;
            wmma::fragment<wmma::matrix_a, 16, 16, 16, h16, wmma::row_major> af;
            wmma::load_matrix_sync(af, As + t * 256, 16);
            #pragma unroll
            for (int nj = 0; nj < 4; nj++) {
                wmma::fragment<wmma::matrix_b, 16, 16, 16, h16, wmma::row_major> bf;
                wmma::load_matrix_sync(bf, Ws + warpN * 64 + nj * 16, 136);
                wmma::mma_sync(acc[mt][nj], af, bf, acc[mt][nj]);
            }
        }
        __syncthreads();
    }

    float* buf = (float*)smem + warp * 320;
    #pragma unroll
    for (int mt = 0; mt < 2; mt++) {
        int t = warpM * 2 + mt;
        #pragma unroll
        for (int nj = 0; nj < 4; nj++) {
            wmma::store_matrix_sync(buf, acc[mt][nj], 20, wmma::mem_row_major);
            __syncwarp();
            #pragma unroll
            for (int l = 0; l < 8; l++) {
                int e = l * 32 + lane;
                int r = e >> 4, c = e & 15;
                int gm = m0 + t * 16 + r;
                int gn = n0 + warpN * 64 + nj * 16 + c;
                float v = buf[r * 20 + c];
                size_t o = (size_t)gm * N + gn;
                if (MODE == 0) {
                    Cf[o] = v;
                    C16[o] = __float2half(v);
                } else if (MODE == 1) {
                    Cf[o] = v + bias[gn];
                } else {
                    float s = bng[gn] * rsqrtf(1.f + EPS);
                    v = resid[o] + fmaxf(v * s + bnb[gn], 0.f);
                    C16[((size_t)(gn >> 4) * BHW + gm) * 16 + (gn & 15)] = __float2half(v);
                }
            }
            __syncwarp();
        }
    }
}

// ---------------- bulk-copy 1-term fp16 3x3 conv ----------------
// block: 256px x 128oc; 512 thr. stage: A[6][66][16]=12672 | W[9][16][136]=39168 = 51840
#define SW_OFF 12672
#define CSTG 51840
#define CONVB_SMEM (2 * CSTG + 64)
__global__ __launch_bounds__(512, 1)
void k_conv_bulk(const h16* __restrict__ inb, int csteps, const h16* __restrict__ wb,
                 const float* __restrict__ bng, const float* __restrict__ bnb,
                 float* __restrict__ out_f, h16* __restrict__ ob) {
    extern __shared__ char dsm[];
    char* aptr = (char*)(((size_t)dsm + 127) & ~(size_t)127);
    unsigned int abase = (unsigned int)__cvta_generic_to_shared(aptr);
    unsigned int mb0 = abase + 2 * CSTG, mb1 = mb0 + 8;

    int tid = threadIdx.x, lane = tid & 31, warp = tid >> 5;
    int warpM = warp >> 1, warpN = warp & 1;
    int b = blockIdx.x >> 4, h0 = (blockIdx.x & 15) << 2;
    int nt = blockIdx.y;
    int oc0 = nt << 7;

    if (tid == 0) { mbar_init(mb0, 1); mbar_init(mb1, 1); }
    // zero-once halos (both buffers)
    if (tid < 12) {
        int r = tid % 6, bufi = tid / 6;
        char* rowp = aptr + bufi * CSTG + r * 2112;
        int grow = h0 + r - 1;
        if (grow < 0 || grow >= HH) {
            for (int i = 0; i < 132; i++) ((float4*)rowp)[i] = make_float4(0, 0, 0, 0);
        } else {
            ((float4*)rowp)[0] = make_float4(0, 0, 0, 0);
            ((float4*)rowp)[1] = make_float4(0, 0, 0, 0);
            ((float4*)(rowp + 2080))[0] = make_float4(0, 0, 0, 0);
            ((float4*)(rowp + 2080))[1] = make_float4(0, 0, 0, 0);
        }
    }
    __syncthreads();

    int nvalid = 0;
    for (int r = 0; r < 6; r++) { int g = h0 + r - 1; if (g >= 0 && g < HH) nvalid++; }
    unsigned int txb = 39168u + (unsigned int)nvalid * 2048u;

    auto issue = [&](int s) {
        unsigned int base = abase + (s & 1) * CSTG;
        unsigned int mb = (s & 1) ? mb1 : mb0;
        mbar_expect(mb, txb);
        bulk_cp(base + SW_OFF, wb + (size_t)(nt * csteps + s) * 19584, 39168, mb);
        for (int r = 0; r < 6; r++) {
            int grow = h0 + r - 1;
            if (grow < 0 || grow >= HH) continue;
            size_t so = ((size_t)(s * BATCH + b) * HH + grow) * WW * 16;
            bulk_cp(base + r * 2112 + 32, inb + so, 2048, mb);
        }
    };

    if (tid == 0) { issue(0); if (csteps > 1) issue(1); }
    int ph[2] = {0, 0};

    wmma::fragment<wmma::accumulator, 16, 16, 16, float> acc[2][4];
    #pragma unroll
    for (int mt = 0; mt < 2; mt++)
        #pragma unroll
        for (int nj = 0; nj < 4; nj++) wmma::fill_fragment(acc[mt][nj], 0.f);

    for (int s = 0; s < csteps; s++) {
        int m = s & 1;
        mbar_wait(m ? mb1 : mb0, ph[m]); ph[m] ^= 1;
        char* base = aptr + m * CSTG;
        h16* As = (h16*)base;
        h16* Ws = (h16*)(base + SW_OFF);

        #pragma unroll
        for (int tap = 0; tap < 9; tap++) {
            int ky = tap / 3, kx = tap % 3;
            wmma::fragment<wmma::matrix_a, 16, 16, 16, h16, wmma::row_major> af[2];
            #pragma unroll
            for (int mt = 0; mt < 2; mt++) {
                int t = warpM * 2 + mt;
                int row_l = t >> 2, px0 = (t & 3) * 16;
                wmma::load_matrix_sync(af[mt], As + ((row_l + ky) * 66 + px0 + kx) * 16, 16);
            }
            #pragma unroll
            for (int nj = 0; nj < 4; nj++) {
                wmma::fragment<wmma::matrix_b, 16, 16, 16, h16, wmma::row_major> bf;
                wmma::load_matrix_sync(bf, Ws + tap * 2176 + warpN * 64 + nj * 16, 136);
                #pragma unroll
                for (int mt = 0; mt < 2; mt++)
                    wmma::mma_sync(acc[mt][nj], af[mt], bf, acc[mt][nj]);
            }
        }
        __syncthreads();
        if (tid == 0 && s + 2 < csteps) issue(s + 2);
    }

    float* buf = (float*)aptr + warp * 320;
    #pragma unroll
    for (int mt = 0; mt < 2; mt++) {
        int t = warpM * 2 + mt;
        int row_l = t >> 2, px0 = (t & 3) * 16;
        int grow = h0 + row_l;
        #pragma unroll
        for (int nj = 0; nj < 4; nj++) {
            wmma::store_matrix_sync(buf, acc[mt][nj], 20, wmma::mem_row_major);
            __syncwarp();
            #pragma unroll
            for (int l = 0; l < 8; l++) {
                int e = l * 32 + lane;
                int r = e >> 4, c = e & 15;
                int gn = oc0 + warpN * 64 + nj * 16 + c;
                int pix = (b * HH + grow) * WW + px0 + r;
                float v = buf[r * 20 + c];
                float sc = bng[gn] * rsqrtf(1.f + EPS);
                v = fmaxf(v * sc + bnb[gn], 0.f);
                if (out_f) out_f[(size_t)pix * CC + gn] = v;
                else ob[((size_t)(gn >> 4) * BHW + pix) * 16 + (gn & 15)] = __float2half(v);
            }
            __syncwarp();
        }
    }
}

// ---------------- classifier ----------------
__global__ void k_classifier(const float* __restrict__ drop_w, float* __restrict__ out) {
    __shared__ float Xs[32][65];
    __shared__ float Ws[KK][33];
    int tid = threadIdx.x;
    int row0 = blockIdx.x * 64;
    int b = row0 >> 12, hw0 = row0 & 4095;
    float acc[5] = {0.f, 0.f, 0.f, 0.f, 0.f};
    for (int c0 = 0; c0 < CC; c0 += 32) {
        for (int idx = tid; idx < 2048; idx += 256) {
            int r = idx >> 5, cc = idx & 31;
            Xs[cc][r] = g_x3[(size_t)(row0 + r) * CC + c0 + cc];
        }
        for (int idx = tid; idx < KK * 32; idx += 256) {
            int k = idx >> 5, cc = idx & 31;
            Ws[k][cc] = drop_w[(size_t)k * CC + c0 + cc];
        }
        __syncthreads();
        #pragma unroll
        for (int si = 0; si < 5; si++) {
            int o = tid + si * 256;
            if (o < KK * 64) {
                int k = o >> 6, r = o & 63;
                float a = acc[si];
                #pragma unroll 8
                for (int cc = 0; cc < 32; cc++) a += Ws[k][cc] * Xs[cc][r];
                acc[si] = a;
            }
        }
        __syncthreads();
    }
    #pragma unroll
    for (int si = 0; si < 5; si++) {
        int o = tid + si * 256;
        if (o < KK * 64) {
            int k = o >> 6, r = o & 63;
            out[((size_t)b * KK + k) * HW + hw0 + r] = acc[si];
        }
    }
}

// ---------------- launch ----------------
#define GSA(p, s) cudaGetSymbolAddress((void**)&p, s)
extern "C" void kernel_launch(void* const* d_in, const int* in_sizes, int n_in,
                              void* d_out, int out_size) {
    const float* M_1   = (const float*)d_in[0];
    const float* F     = (const float*)d_in[1];
    const float* I     = (const float*)d_in[2];
    const float* R     = (const float*)d_in[3];
    const float* lg_w1 = (const float*)d_in[4];
    const float* lg_w2 = (const float*)d_in[5];
    const float* fuse_w= (const float*)d_in[6];
    const float* fuse_b= (const float*)d_in[7];
    const float* q_w   = (const float*)d_in[8];
    const float* q_b   = (const float*)d_in[9];
    const float* k_w   = (const float*)d_in[10];
    const float* k_b   = (const float*)d_in[11];
    const float* v_w   = (const float*)d_in[12];
    const float* v_b   = (const float*)d_in[13];
    const float* c1_w  = (const float*)d_in[14];
    const float* bn1_g = (const float*)d_in[15];
    const float* bn1_b = (const float*)d_in[16];
    const float* c2_w  = (const float*)d_in[17];
    const float* bn2_g = (const float*)d_in[18];
    const float* bn2_b = (const float*)d_in[19];
    const float* c3_w  = (const float*)d_in[20];
    const float* bn3_g = (const float*)d_in[21];
    const float* bn3_b = (const float*)d_in[22];
    const float* drop_w= (const float*)d_in[23];
    float* out = (float*)d_out;

    float *p_Fnhwc, *p_Fl2, *p_Fg, *p_q, *p_k, *p_v, *p_x3;
    h16 *p_F16, *p_h16, *p_Fl216, *p_Fs16, *p_Fo1b, *p_catb, *p_w2b, *p_w3b;
    h16 *p_qw, *p_kw, *p_lgw, *p_c1;
    GSA(p_Fnhwc, g_Fnhwc); GSA(p_Fl2, g_Fl2); GSA(p_Fg, g_Fg);
    GSA(p_q, g_query); GSA(p_k, g_key); GSA(p_v, g_value); GSA(p_x3, g_x3);
    GSA(p_F16, g_F16); GSA(p_h16, g_h16); GSA(p_Fl216, g_Fl216); GSA(p_Fs16, g_Fs16);
    GSA(p_Fo1b, g_Fo1b); GSA(p_catb, g_catb);
    GSA(p_w2b, g_w2b); GSA(p_w3b, g_w3b);
    GSA(p_qw, g_qw16); GSA(p_kw, g_kw16); GSA(p_lgw, g_lgw16); GSA(p_c1, g_c116);

    dim3 blk32(32, 8);
    const int GEMM_SMEM = 2 * GSTAGE_B;
    cudaFuncSetAttribute(k_conv_bulk, cudaFuncAttributeMaxDynamicSharedMemorySize, CONVB_SMEM);
    cudaFuncSetAttribute(k_gemm_mma<0>, cudaFuncAttributeMaxDynamicSharedMemorySize, GEMM_SMEM);
    cudaFuncSetAttribute(k_gemm_mma<1>, cudaFuncAttributeMaxDynamicSharedMemorySize, GEMM_SMEM);
    cudaFuncSetAttribute(k_gemm_mma<2>, cudaFuncAttributeMaxDynamicSharedMemorySize, GEMM_SMEM);

    k_wprep<<<(4 * 32 * 19584 + 255) / 256, 256>>>(c2_w, p_w2b, 512, 32);
    k_wprep<<<(int)(((size_t)4 * 160 * 19584 + 255) / 256), 256>>>(c3_w, p_w3b, 2560, 160);
    k_wt16<<<512, 256>>>(q_w, p_qw, 512, 256);
    k_wt16<<<512, 256>>>(k_w, p_kw, 512, 256);
    k_wt16<<<1024, 256>>>(lg_w2, p_lgw, 512, 512);
    k_wt16<<<512, 256>>>(c1_w, p_c1, 256, 512);

    k_transpose_f<<<dim3(HW / 32, CC / 32, BATCH), blk32>>>(F, p_Fnhwc, p_F16);
    k_transpose_m1<<<dim3(HW / 32, 2048 / 32, BATCH), blk32>>>(M_1, p_catb);
    k_patch_fl<<<BATCH * PP, 256>>>(I, R);
    k_lg1<<<dim3(CC / 64, BATCH * KK), 256>>>(lg_w1);

    // Fl2 = h @ lg_w2^T
    k_gemm_mma<0><<<dim3(4, 19), 512, GEMM_SMEM>>>(
        p_h16, p_lgw, 512, 512, p_Fl2, p_Fl216, nullptr, nullptr, nullptr, nullptr);
    k_fuse<<<BATCH * KK, CC>>>(fuse_w, fuse_b);

    k_gemm_mma<1><<<dim3(2, 64), 512, GEMM_SMEM>>>(
        p_F16, p_qw, 512, 256, p_q, nullptr, q_b, nullptr, nullptr, nullptr);
    k_gemm_mma<1><<<dim3(2, 19), 512, GEMM_SMEM>>>(
        p_Fl216, p_kw, 512, 256, p_k, nullptr, k_b, nullptr, nullptr, nullptr);
    k_gemm_v<<<dim3(DD / 64, 2), 256>>>(p_Fg, v_w, p_v, BATCH * KK, DD, CC, v_b);

    k_attn<<<BATCH * PP, 256>>>();

    // Fo1 = F + relu(bn1(F_s @ c1^T)) -> blocked fp16
    k_gemm_mma<2><<<dim3(4, 64), 512, GEMM_SMEM>>>(
        p_Fs16, p_c1, 256, 512, nullptr, p_Fo1b, nullptr, bn1_g, bn1_b, p_Fnhwc);

    k_conv_bulk<<<dim3(BATCH * 16, 4), 512, CONVB_SMEM>>>(
        p_Fo1b, 32, p_w2b, bn2_g, bn2_b, nullptr, p_catb);
    k_conv_bulk<<<dim3(BATCH * 16, 4), 512, CONVB_SMEM>>>(
        p_catb, 160, p_w3b, bn3_g, bn3_b, p_x3, nullptr);

    k_classifier<<<(BATCH * HW) / 64, 256>>>(drop_w, out);
}

// round 12
// speedup vs baseline: 2.4474x; 1.0098x over previous
#include <cuda_runtime.h>
#include <cuda_fp16.h>
#include <mma.h>
#include <math.h>
#include <stdint.h>

using namespace nvcuda;
typedef __half h16;

#define EPS 1e-5f
#define BATCH 4
#define HH 64
#define WW 64
#define HW 4096
#define BHW 16384
#define CC 512
#define KK 19
#define PP 64
#define NN 64
#define DD 256

__device__ float g_Fnhwc[BATCH * HW * CC];
__device__ float g_Fl[BATCH * PP * KK * CC];
__device__ float g_Fg[BATCH * KK * CC];
__device__ float g_query[BATCH * HW * DD];
__device__ float g_key[BATCH * PP * KK * DD];
__device__ float g_value[BATCH * KK * DD];
__device__ float g_x3[BATCH * HW * CC];

// single-fp16 activations
__device__ h16 g_F16[BATCH * HW * CC];
__device__ h16 g_h16[BATCH * PP * KK * CC];
__device__ h16 g_Fl216[BATCH * PP * KK * CC];
__device__ h16 g_Fs16[BATCH * HW * DD];
// channel-blocked activations: [chunk][B][H][W][16]
__device__ h16 g_Fo1b[32 * BHW * 16];
__device__ h16 g_catb[(size_t)160 * BHW * 16];

// conv weights blocked for bulk copy: [ntile(4)][chunk][tap9][k16][136]
__device__ h16 g_w2b[4 * 32 * 19584];
__device__ h16 g_w3b[(size_t)4 * 160 * 19584];
// GEMM weights [K][N], single fp16
__device__ h16 g_qw16[512 * 256];
__device__ h16 g_kw16[512 * 256];
__device__ h16 g_lgw16[512 * 512];
__device__ h16 g_c116[256 * 512];

__device__ __forceinline__ void cpa16(void* sdst, const void* gsrc) {
    unsigned int s = (unsigned int)__cvta_generic_to_shared(sdst);
    asm volatile("cp.async.cg.shared.global [%0], [%1], 16;" :: "r"(s), "l"(gsrc));
}
__device__ __forceinline__ void cpa_commit() { asm volatile("cp.async.commit_group;"); }
template <int N>
__device__ __forceinline__ void cpa_wait() { asm volatile("cp.async.wait_group %0;" :: "n"(N)); }

__device__ __forceinline__ void bulk_cp(unsigned int sdst, const void* gsrc,
                                        unsigned int bytes, unsigned int mbar) {
    asm volatile(
        "cp.async.bulk.shared::cta.global.mbarrier::complete_tx::bytes [%0], [%1], %2, [%3];"
        :: "r"(sdst), "l"(gsrc), "r"(bytes), "r"(mbar) : "memory");
}
__device__ __forceinline__ void mbar_init(unsigned int m, unsigned int c) {
    asm volatile("mbarrier.init.shared.b64 [%0], %1;" :: "r"(m), "r"(c) : "memory");
}
__device__ __forceinline__ void mbar_expect(unsigned int m, unsigned int tx) {
    asm volatile("mbarrier.arrive.expect_tx.shared.b64 _, [%0], %1;" :: "r"(m), "r"(tx) : "memory");
}
__device__ __forceinline__ void mbar_wait(unsigned int m, unsigned int par) {
    unsigned int done;
    asm volatile(
        "{\n\t.reg .pred p;\n\t"
        "mbarrier.try_wait.parity.acquire.cta.shared::cta.b64 p, [%1], %2;\n\t"
        "selp.b32 %0, 1, 0, p;\n\t}" : "=r"(done) : "r"(m), "r"(par) : "memory");
    if (!done) {
        asm volatile(
            "{\n\t.reg .pred P1;\n\tWL_%=:\n\t"
            "mbarrier.try_wait.parity.acquire.cta.shared::cta.b64 P1, [%0], %1, 0x989680;\n\t"
            "@P1 bra.uni WD_%=;\n\tbra.uni WL_%=;\n\tWD_%=:\n\t}"
            :: "r"(m), "r"(par) : "memory");
    }
}

// ---------------- transposes ----------------
__global__ void k_transpose_f(const float* __restrict__ in, float* __restrict__ out,
                              h16* __restrict__ o16) {
    __shared__ float tile[32][33];
    int b = blockIdx.z, hw0 = blockIdx.x * 32, c0 = blockIdx.y * 32;
    int tx = threadIdx.x, ty = threadIdx.y;
    for (int i = ty; i < 32; i += 8)
        tile[i][tx] = in[((size_t)b * CC + c0 + i) * HW + hw0 + tx];
    __syncthreads();
    for (int i = ty; i < 32; i += 8) {
        float v = tile[tx][i];
        size_t o = ((size_t)b * HW + hw0 + i) * CC + c0 + tx;
        out[o] = v;
        o16[o] = __float2half(v);
    }
}
__global__ void k_transpose_m1(const float* __restrict__ in, h16* __restrict__ ob) {
    __shared__ float tile[32][33];
    int b = blockIdx.z, hw0 = blockIdx.x * 32, c0 = blockIdx.y * 32;
    int tx = threadIdx.x, ty = threadIdx.y;
    for (int i = ty; i < 32; i += 8)
        tile[i][tx] = in[((size_t)b * 2048 + c0 + i) * HW + hw0 + tx];
    __syncthreads();
    for (int i = ty; i < 32; i += 8) {
        int cg = 512 + c0 + tx;
        size_t o = ((size_t)(cg >> 4) * BHW + (size_t)b * HW + hw0 + i) * 16 + (cg & 15);
        ob[o] = __float2half(tile[tx][i]);
    }
}

// conv weight prep: OIHW -> [ntile][chunk][tap9][k16][136]
__global__ void k_wprep(const float* __restrict__ w, h16* __restrict__ dst,
                        int Cin, int csteps) {
    size_t d = (size_t)blockIdx.x * 256 + threadIdx.x;
    size_t total = (size_t)4 * csteps * 19584;
    if (d >= total) return;
    int oc = d % 136;
    size_t r = d / 136;
    int k = r % 16; r /= 16;
    int tap = r % 9; r /= 9;
    int ch = r % csteps;
    int nt = r / csteps;
    h16 outv = __float2half(0.f);
    if (oc < 128)
        outv = __float2half(w[((size_t)(nt * 128 + oc) * Cin + ch * 16 + k) * 9 + tap]);
    dst[d] = outv;
}
__global__ void k_wt16(const float* __restrict__ w, h16* __restrict__ o16, int K, int N) {
    int d = blockIdx.x * 256 + threadIdx.x;
    if (d >= K * N) return;
    int k = d / N, n = d % N;
    o16[d] = __float2half(w[(size_t)n * K + k]);
}

// ---------------- patch softmax + F_l ----------------
__global__ void k_patch_fl(const float* __restrict__ I, const float* __restrict__ R) {
    int bp = blockIdx.x, b = bp >> 6, p = bp & 63;
    int ph = p >> 3, pw = p & 7, tid = threadIdx.x;
    __shared__ float lg[KK][NN];
    __shared__ float pix[NN][20];
    __shared__ float bc[KK];
    __shared__ float Fp[NN][65];
    for (int idx = tid; idx < KK * NN; idx += 256) {
        int k = idx / NN, n = idx % NN;
        int h = ph * 8 + (n >> 3), w = pw * 8 + (n & 7);
        lg[k][n] = I[(((size_t)b * KK + k) * HH + h) * WW + w];
    }
    if (tid < KK) bc[tid] = R[((size_t)b * KK + tid) * PP + p];
    __syncthreads();
    if (tid < KK) {
        float mx = -1e30f;
        for (int n = 0; n < NN; n++) mx = fmaxf(mx, lg[tid][n]);
        float s = 0.f;
        for (int n = 0; n < NN; n++) { float e = __expf(lg[tid][n] - mx); pix[n][tid] = e; s += e; }
        float inv = 1.f / s;
        for (int n = 0; n < NN; n++) pix[n][tid] *= inv;
    }
    __syncthreads();
    for (int c0 = 0; c0 < CC; c0 += 64) {
        for (int idx = tid; idx < NN * 64; idx += 256) {
            int n = idx >> 6, cc = idx & 63;
            int h = ph * 8 + (n >> 3), w = pw * 8 + (n & 7);
            Fp[n][cc] = g_Fnhwc[((size_t)b * HW + h * WW + w) * CC + c0 + cc];
        }
        __syncthreads();
        for (int o = tid; o < KK * 64; o += 256) {
            int k = o >> 6, cc = o & 63;
            float acc = 0.f;
            #pragma unroll 8
            for (int n = 0; n < NN; n++) acc += pix[n][k] * Fp[n][cc];
            g_Fl[((size_t)bp * KK + k) * CC + c0 + cc] = acc * bc[k];
        }
        __syncthreads();
    }
}

__global__ void k_lg1(const float* __restrict__ lg_w1) {
    int c0 = blockIdx.x * 64, bk = blockIdx.y;
    int b = bk / KK, k = bk % KK, tid = threadIdx.x;
    __shared__ float w1[64][64];
    __shared__ float Fl[64][65];
    for (int idx = tid; idx < 4096; idx += 256) w1[idx >> 6][idx & 63] = lg_w1[idx];
    for (int idx = tid; idx < 4096; idx += 256) {
        int p = idx >> 6, cc = idx & 63;
        Fl[p][cc] = g_Fl[(((size_t)b * PP + p) * KK + k) * CC + c0 + cc];
    }
    __syncthreads();
    for (int o = tid; o < 4096; o += 256) {
        int q = o >> 6, cc = o & 63;
        float acc = Fl[q][cc];
        #pragma unroll 8
        for (int p = 0; p < 64; p++) acc += w1[q][p] * Fl[p][cc];
        g_h16[(((size_t)b * PP + q) * KK + k) * CC + c0 + cc] = __float2half(fmaxf(acc, 0.f));
    }
}

__global__ void k_gemm_v(const float* __restrict__ A, const float* __restrict__ Bw,
                         float* __restrict__ C, int M, int N, int K,
                         const float* __restrict__ bias) {
    __shared__ float As[16][68];
    __shared__ float Bs[16][68];
    int m0 = blockIdx.y * 64, n0 = blockIdx.x * 64, tid = threadIdx.x;
    int tx = tid & 15, ty = tid >> 4;
    float acc[4][4] = {};
    for (int k0 = 0; k0 < K; k0 += 16) {
        for (int idx = tid; idx < 1024; idx += 256) {
            int i = idx >> 4, kk = idx & 15;
            int m = m0 + i;
            As[kk][i] = (m < M) ? A[(size_t)m * K + k0 + kk] : 0.f;
        }
        for (int idx = tid; idx < 1024; idx += 256) {
            int j = idx >> 4, kk = idx & 15;
            Bs[kk][j] = Bw[(size_t)(n0 + j) * K + k0 + kk];
        }
        __syncthreads();
        #pragma unroll
        for (int kk = 0; kk < 16; kk++) {
            float a[4], bv[4];
            #pragma unroll
            for (int i = 0; i < 4; i++) a[i] = As[kk][ty * 4 + i];
            #pragma unroll
            for (int j = 0; j < 4; j++) bv[j] = Bs[kk][tx * 4 + j];
            #pragma unroll
            for (int i = 0; i < 4; i++)
                #pragma unroll
                for (int j = 0; j < 4; j++) acc[i][j] += a[i] * bv[j];
        }
        __syncthreads();
    }
    #pragma unroll
    for (int i = 0; i < 4; i++) {
        int m = m0 + ty * 4 + i;
        if (m >= M) continue;
        #pragma unroll
        for (int j = 0; j < 4; j++)
            C[(size_t)m * N + n0 + tx * 4 + j] = acc[i][j] + bias[n0 + tx * 4 + j];
    }
}

__global__ void k_fuse(const float* __restrict__ fw, const float* __restrict__ fb) {
    int bk = blockIdx.x, c = threadIdx.x;
    int b = bk / KK, k = bk % KK;
    float acc = fb[0];
    #pragma unroll 8
    for (int p = 0; p < PP; p++)
        acc += fw[p] * __half2float(g_Fl216[(((size_t)b * PP + p) * KK + k) * CC + c]);
    g_Fg[(size_t)bk * CC + c] = acc;
}

__global__ void k_attn() {
    int bp = blockIdx.x, b = bp >> 6, p = bp & 63;
    int ph = p >> 3, pw = p & 7, tid = threadIdx.x;
    __shared__ float ks[KK][DD];
    __shared__ float vs[KK][DD];
    for (int idx = tid; idx < KK * DD; idx += 256)
        ((float*)ks)[idx] = g_key[(size_t)bp * KK * DD + idx];
    for (int idx = tid; idx < KK * DD; idx += 256)
        ((float*)vs)[idx] = g_value[(size_t)b * KK * DD + idx];
    __syncthreads();
    int warp = tid >> 5, lane = tid & 31;
    for (int n = warp; n < NN; n += 8) {
        int h = ph * 8 + (n >> 3), w = pw * 8 + (n & 7);
        const float* qrow = &g_query[((size_t)b * HW + h * WW + w) * DD];
        float qr[8];
        #pragma unroll
        for (int i = 0; i < 8; i++) qr[i] = qrow[i * 32 + lane];
        float acc[KK];
        #pragma unroll
        for (int k = 0; k < KK; k++) acc[k] = 0.f;
        #pragma unroll
        for (int i = 0; i < 8; i++) {
            float qd = qr[i];
            #pragma unroll
            for (int k = 0; k < KK; k++) acc[k] += qd * ks[k][i * 32 + lane];
        }
        #pragma unroll
        for (int k = 0; k < KK; k++)
            #pragma unroll
            for (int off = 16; off > 0; off >>= 1)
                acc[k] += __shfl_xor_sync(0xFFFFFFFFu, acc[k], off);
        float mx = -1e30f;
        #pragma unroll
        for (int k = 0; k < KK; k++) mx = fmaxf(mx, acc[k]);
        float sum = 0.f;
        #pragma unroll
        for (int k = 0; k < KK; k++) { acc[k] = __expf(acc[k] - mx); sum += acc[k]; }
        float inv = 1.f / sum;
        #pragma unroll
        for (int k = 0; k < KK; k++) acc[k] *= inv;
        size_t ob = ((size_t)b * HW + h * WW + w) * DD;
        #pragma unroll
        for (int i = 0; i < 8; i++) {
            int d = i * 32 + lane;
            float o = 0.f;
            #pragma unroll
            for (int k = 0; k < KK; k++) o += acc[k] * vs[k][d];
            g_Fs16[ob + d] = __float2half(o);
        }
    }
}

// ---------------- 1-term fp16 wmma GEMM ----------------
#define GSTAGE_B 12544
template <int MODE>
__global__ __launch_bounds__(512)
void k_gemm_mma(const h16* __restrict__ Ag, const h16* __restrict__ Wt,
                int K, int N,
                float* __restrict__ Cf, h16* __restrict__ C16,
                const float* __restrict__ bias,
                const float* __restrict__ bng, const float* __restrict__ bnb,
                const float* __restrict__ resid) {
    extern __shared__ char smem[];
    int n0 = blockIdx.x * 128, m0 = blockIdx.y * 256;
    int tid = threadIdx.x, lane = tid & 31, warp = tid >> 5;
    int warpM = warp >> 1, warpN = warp & 1;
    int iters = K >> 4;

    wmma::fragment<wmma::accumulator, 16, 16, 16, float> acc[2][4];
    #pragma unroll
    for (int mt = 0; mt < 2; mt++)
        #pragma unroll
        for (int nj = 0; nj < 4; nj++) wmma::fill_fragment(acc[mt][nj], 0.f);

    auto issue = [&](int it) {
        int k0 = it << 4;
        char* base = smem + (it & 1) * GSTAGE_B;
        h16* As = (h16*)base;
        h16* Ws = (h16*)(base + 8192);
        {
            int flat = tid * 8;
            int r = flat >> 4, c8 = flat & 15;
            cpa16(As + flat, Ag + (size_t)(m0 + r) * K + k0 + c8);
        }
        if (tid < 256) {
            int flat = tid * 8;
            int kk = flat >> 7, n8 = flat & 127;
            cpa16(Ws + kk * 136 + n8, Wt + (size_t)(k0 + kk) * N + n0 + n8);
        }
        cpa_commit();
    };

    issue(0);
    for (int it = 0; it < iters; it++) {
        cpa_wait<0>();
        __syncthreads();
        if (it + 1 < iters) issue(it + 1);
        char* base = smem + (it & 1) * GSTAGE_B;
        h16* As = (h16*)base;
        h16* Ws = (h16*)(base + 8192);
        #pragma unroll
        for (int mt = 0; mt < 2; mt++) {
            int t = warpM * 2 + mt;
            wmma::fragment<wmma::matrix_a, 16, 16, 16, h16, wmma::row_major> af;
            wmma::load_matrix_sync(af, As + t * 256, 16);
            #pragma unroll
            for (int nj = 0; nj < 4; nj++) {
                wmma::fragment<wmma::matrix_b, 16, 16, 16, h16, wmma::row_major> bf;
                wmma::load_matrix_sync(bf, Ws + warpN * 64 + nj * 16, 136);
                wmma::mma_sync(acc[mt][nj], af, bf, acc[mt][nj]);
            }
        }
        __syncthreads();
    }

    float* buf = (float*)smem + warp * 320;
    #pragma unroll
    for (int mt = 0; mt < 2; mt++) {
        int t = warpM * 2 + mt;
        #pragma unroll
        for (int nj = 0; nj < 4; nj++) {
            wmma::store_matrix_sync(buf, acc[mt][nj], 20, wmma::mem_row_major);
            __syncwarp();
            #pragma unroll
            for (int l = 0; l < 8; l++) {
                int e = l * 32 + lane;
                int r = e >> 4, c = e & 15;
                int gm = m0 + t * 16 + r;
                int gn = n0 + warpN * 64 + nj * 16 + c;
                float v = buf[r * 20 + c];
                size_t o = (size_t)gm * N + gn;
                if (MODE == 0) {
                    C16[o] = __float2half(v);
                } else if (MODE == 1) {
                    Cf[o] = v + bias[gn];
                } else {
                    float s = bng[gn] * rsqrtf(1.f + EPS);
                    v = resid[o] + fmaxf(v * s + bnb[gn], 0.f);
                    C16[((size_t)(gn >> 4) * BHW + gm) * 16 + (gn & 15)] = __float2half(v);
                }
            }
            __syncwarp();
        }
    }
}

// ---------------- bulk-copy 1-term fp16 3x3 conv ----------------
#define SW_OFF 12672
#define CSTG 51840
#define CONVB_SMEM (2 * CSTG + 64)
__global__ __launch_bounds__(512, 1)
void k_conv_bulk(const h16* __restrict__ inb, int csteps, const h16* __restrict__ wb,
                 const float* __restrict__ bng, const float* __restrict__ bnb,
                 float* __restrict__ out_f, h16* __restrict__ ob) {
    extern __shared__ char dsm[];
    char* aptr = (char*)(((size_t)dsm + 127) & ~(size_t)127);
    unsigned int abase = (unsigned int)__cvta_generic_to_shared(aptr);
    unsigned int mb0 = abase + 2 * CSTG, mb1 = mb0 + 8;

    int tid = threadIdx.x, lane = tid & 31, warp = tid >> 5;
    int warpM = warp >> 1, warpN = warp & 1;
    int b = blockIdx.x >> 4, h0 = (blockIdx.x & 15) << 2;
    int nt = blockIdx.y;
    int oc0 = nt << 7;

    if (tid == 0) { mbar_init(mb0, 1); mbar_init(mb1, 1); }
    if (tid < 12) {
        int r = tid % 6, bufi = tid / 6;
        char* rowp = aptr + bufi * CSTG + r * 2112;
        int grow = h0 + r - 1;
        if (grow < 0 || grow >= HH) {
            for (int i = 0; i < 132; i++) ((float4*)rowp)[i] = make_float4(0, 0, 0, 0);
        } else {
            ((float4*)rowp)[0] = make_float4(0, 0, 0, 0);
            ((float4*)rowp)[1] = make_float4(0, 0, 0, 0);
            ((float4*)(rowp + 2080))[0] = make_float4(0, 0, 0, 0);
            ((float4*)(rowp + 2080))[1] = make_float4(0, 0, 0, 0);
        }
    }
    __syncthreads();

    int nvalid = 0;
    for (int r = 0; r < 6; r++) { int g = h0 + r - 1; if (g >= 0 && g < HH) nvalid++; }
    unsigned int txb = 39168u + (unsigned int)nvalid * 2048u;

    auto issue = [&](int s) {
        unsigned int base = abase + (s & 1) * CSTG;
        unsigned int mb = (s & 1) ? mb1 : mb0;
        mbar_expect(mb, txb);
        bulk_cp(base + SW_OFF, wb + (size_t)(nt * csteps + s) * 19584, 39168, mb);
        for (int r = 0; r < 6; r++) {
            int grow = h0 + r - 1;
            if (grow < 0 || grow >= HH) continue;
            size_t so = ((size_t)(s * BATCH + b) * HH + grow) * WW * 16;
            bulk_cp(base + r * 2112 + 32, inb + so, 2048, mb);
        }
    };

    if (tid == 0) { issue(0); if (csteps > 1) issue(1); }
    int ph[2] = {0, 0};

    wmma::fragment<wmma::accumulator, 16, 16, 16, float> acc[2][4];
    #pragma unroll
    for (int mt = 0; mt < 2; mt++)
        #pragma unroll
        for (int nj = 0; nj < 4; nj++) wmma::fill_fragment(acc[mt][nj], 0.f);

    for (int s = 0; s < csteps; s++) {
        int m = s & 1;
        mbar_wait(m ? mb1 : mb0, ph[m]); ph[m] ^= 1;
        char* base = aptr + m * CSTG;
        h16* As = (h16*)base;
        h16* Ws = (h16*)(base + SW_OFF);

        #pragma unroll
        for (int tap = 0; tap < 9; tap++) {
            int ky = tap / 3, kx = tap % 3;
            wmma::fragment<wmma::matrix_a, 16, 16, 16, h16, wmma::row_major> af[2];
            #pragma unroll
            for (int mt = 0; mt < 2; mt++) {
                int t = warpM * 2 + mt;
                int row_l = t >> 2, px0 = (t & 3) * 16;
                wmma::load_matrix_sync(af[mt], As + ((row_l + ky) * 66 + px0 + kx) * 16, 16);
            }
            #pragma unroll
            for (int nj = 0; nj < 4; nj++) {
                wmma::fragment<wmma::matrix_b, 16, 16, 16, h16, wmma::row_major> bf;
                wmma::load_matrix_sync(bf, Ws + tap * 2176 + warpN * 64 + nj * 16, 136);
                #pragma unroll
                for (int mt = 0; mt < 2; mt++)
                    wmma::mma_sync(acc[mt][nj], af[mt], bf, acc[mt][nj]);
            }
        }
        __syncthreads();
        if (tid == 0 && s + 2 < csteps) issue(s + 2);
    }

    float* buf = (float*)aptr + warp * 320;
    #pragma unroll
    for (int mt = 0; mt < 2; mt++) {
        int t = warpM * 2 + mt;
        int row_l = t >> 2, px0 = (t & 3) * 16;
        int grow = h0 + row_l;
        #pragma unroll
        for (int nj = 0; nj < 4; nj++) {
            wmma::store_matrix_sync(buf, acc[mt][nj], 20, wmma::mem_row_major);
            __syncwarp();
            #pragma unroll
            for (int l = 0; l < 8; l++) {
                int e = l * 32 + lane;
                int r = e >> 4, c = e & 15;
                int gn = oc0 + warpN * 64 + nj * 16 + c;
                int pix = (b * HH + grow) * WW + px0 + r;
                float v = buf[r * 20 + c];
                float sc = bng[gn] * rsqrtf(1.f + EPS);
                v = fmaxf(v * sc + bnb[gn], 0.f);
                if (out_f) out_f[(size_t)pix * CC + gn] = v;
                else ob[((size_t)(gn >> 4) * BHW + pix) * 16 + (gn & 15)] = __float2half(v);
            }
            __syncwarp();
        }
    }
}

// ---------------- classifier ----------------
__global__ void k_classifier(const float* __restrict__ drop_w, float* __restrict__ out) {
    __shared__ float Xs[32][65];
    __shared__ float Ws[KK][33];
    int tid = threadIdx.x;
    int row0 = blockIdx.x * 64;
    int b = row0 >> 12, hw0 = row0 & 4095;
    float acc[5] = {0.f, 0.f, 0.f, 0.f, 0.f};
    for (int c0 = 0; c0 < CC; c0 += 32) {
        for (int idx = tid; idx < 2048; idx += 256) {
            int r = idx >> 5, cc = idx & 31;
            Xs[cc][r] = g_x3[(size_t)(row0 + r) * CC + c0 + cc];
        }
        for (int idx = tid; idx < KK * 32; idx += 256) {
            int k = idx >> 5, cc = idx & 31;
            Ws[k][cc] = drop_w[(size_t)k * CC + c0 + cc];
        }
        __syncthreads();
        #pragma unroll
        for (int si = 0; si < 5; si++) {
            int o = tid + si * 256;
            if (o < KK * 64) {
                int k = o >> 6, r = o & 63;
                float a = acc[si];
                #pragma unroll 8
                for (int cc = 0; cc < 32; cc++) a += Ws[k][cc] * Xs[cc][r];
                acc[si] = a;
            }
        }
        __syncthreads();
    }
    #pragma unroll
    for (int si = 0; si < 5; si++) {
        int o = tid + si * 256;
        if (o < KK * 64) {
            int k = o >> 6, r = o & 63;
            out[((size_t)b * KK + k) * HW + hw0 + r] = acc[si];
        }
    }
}

// ---------------- launch (multi-stream graph) ----------------
#define GSA(p, s) cudaGetSymbolAddress((void**)&p, s)
extern "C" void kernel_launch(void* const* d_in, const int* in_sizes, int n_in,
                              void* d_out, int out_size) {
    const float* M_1   = (const float*)d_in[0];
    const float* F     = (const float*)d_in[1];
    const float* I     = (const float*)d_in[2];
    const float* R     = (const float*)d_in[3];
    const float* lg_w1 = (const float*)d_in[4];
    const float* lg_w2 = (const float*)d_in[5];
    const float* fuse_w= (const float*)d_in[6];
    const float* fuse_b= (const float*)d_in[7];
    const float* q_w   = (const float*)d_in[8];
    const float* q_b   = (const float*)d_in[9];
    const float* k_w   = (const float*)d_in[10];
    const float* k_b   = (const float*)d_in[11];
    const float* v_w   = (const float*)d_in[12];
    const float* v_b   = (const float*)d_in[13];
    const float* c1_w  = (const float*)d_in[14];
    const float* bn1_g = (const float*)d_in[15];
    const float* bn1_b = (const float*)d_in[16];
    const float* c2_w  = (const float*)d_in[17];
    const float* bn2_g = (const float*)d_in[18];
    const float* bn2_b = (const float*)d_in[19];
    const float* c3_w  = (const float*)d_in[20];
    const float* bn3_g = (const float*)d_in[21];
    const float* bn3_b = (const float*)d_in[22];
    const float* drop_w= (const float*)d_in[23];
    float* out = (float*)d_out;

    float *p_Fnhwc, *p_Fg, *p_q, *p_k, *p_v, *p_x3;
    h16 *p_F16, *p_h16, *p_Fl216, *p_Fs16, *p_Fo1b, *p_catb, *p_w2b, *p_w3b;
    h16 *p_qw, *p_kw, *p_lgw, *p_c1;
    GSA(p_Fnhwc, g_Fnhwc); GSA(p_Fg, g_Fg);
    GSA(p_q, g_query); GSA(p_k, g_key); GSA(p_v, g_value); GSA(p_x3, g_x3);
    GSA(p_F16, g_F16); GSA(p_h16, g_h16); GSA(p_Fl216, g_Fl216); GSA(p_Fs16, g_Fs16);
    GSA(p_Fo1b, g_Fo1b); GSA(p_catb, g_catb);
    GSA(p_w2b, g_w2b); GSA(p_w3b, g_w3b);
    GSA(p_qw, g_qw16); GSA(p_kw, g_kw16); GSA(p_lgw, g_lgw16); GSA(p_c1, g_c116);

    static bool init = false;
    static cudaStream_t s1, s2;
    static cudaEvent_t eFork, eTf, eLgw, eKw, eQw, eC1, eW2, eM1, eW3, eQ;
    if (!init) {
        cudaStreamCreateWithFlags(&s1, cudaStreamNonBlocking);
        cudaStreamCreateWithFlags(&s2, cudaStreamNonBlocking);
        cudaEventCreateWithFlags(&eFork, cudaEventDisableTiming);
        cudaEventCreateWithFlags(&eTf,   cudaEventDisableTiming);
        cudaEventCreateWithFlags(&eLgw,  cudaEventDisableTiming);
        cudaEventCreateWithFlags(&eKw,   cudaEventDisableTiming);
        cudaEventCreateWithFlags(&eQw,   cudaEventDisableTiming);
        cudaEventCreateWithFlags(&eC1,   cudaEventDisableTiming);
        cudaEventCreateWithFlags(&eW2,   cudaEventDisableTiming);
        cudaEventCreateWithFlags(&eM1,   cudaEventDisableTiming);
        cudaEventCreateWithFlags(&eW3,   cudaEventDisableTiming);
        cudaEventCreateWithFlags(&eQ,    cudaEventDisableTiming);
        cudaFuncSetAttribute(k_conv_bulk, cudaFuncAttributeMaxDynamicSharedMemorySize, CONVB_SMEM);
        cudaFuncSetAttribute(k_gemm_mma<0>, cudaFuncAttributeMaxDynamicSharedMemorySize, 2 * GSTAGE_B);
        cudaFuncSetAttribute(k_gemm_mma<1>, cudaFuncAttributeMaxDynamicSharedMemorySize, 2 * GSTAGE_B);
        cudaFuncSetAttribute(k_gemm_mma<2>, cudaFuncAttributeMaxDynamicSharedMemorySize, 2 * GSTAGE_B);
        init = true;
    }
    const int GEMM_SMEM = 2 * GSTAGE_B;
    dim3 blk32(32, 8);

    // fork side stream s1 (weight preps + M1 transpose)
    cudaEventRecord(eFork, 0);
    cudaStreamWaitEvent(s1, eFork, 0);
    cudaStreamWaitEvent(s2, eFork, 0);
    k_wt16<<<1024, 256, 0, s1>>>(lg_w2, p_lgw, 512, 512);
    cudaEventRecord(eLgw, s1);
    k_wt16<<<512, 256, 0, s1>>>(k_w, p_kw, 512, 256);
    cudaEventRecord(eKw, s1);
    k_wt16<<<512, 256, 0, s1>>>(q_w, p_qw, 512, 256);
    cudaEventRecord(eQw, s1);
    k_wt16<<<512, 256, 0, s1>>>(c1_w, p_c1, 256, 512);
    cudaEventRecord(eC1, s1);
    k_wprep<<<(4 * 32 * 19584 + 255) / 256, 256, 0, s1>>>(c2_w, p_w2b, 512, 32);
    cudaEventRecord(eW2, s1);
    k_transpose_m1<<<dim3(HW / 32, 2048 / 32, BATCH), blk32, 0, s1>>>(M_1, p_catb);
    cudaEventRecord(eM1, s1);
    k_wprep<<<(int)(((size_t)4 * 160 * 19584 + 255) / 256), 256, 0, s1>>>(c3_w, p_w3b, 2560, 160);
    cudaEventRecord(eW3, s1);

    // main chain (stream 0)
    k_transpose_f<<<dim3(HW / 32, CC / 32, BATCH), blk32>>>(F, p_Fnhwc, p_F16);
    cudaEventRecord(eTf, 0);
    k_patch_fl<<<BATCH * PP, 256>>>(I, R);
    k_lg1<<<dim3(CC / 64, BATCH * KK), 256>>>(lg_w1);

    // query GEMM on s2 (needs F16 + qw)
    cudaStreamWaitEvent(s2, eTf, 0);
    cudaStreamWaitEvent(s2, eQw, 0);
    k_gemm_mma<1><<<dim3(2, 64), 512, GEMM_SMEM, s2>>>(
        p_F16, p_qw, 512, 256, p_q, nullptr, q_b, nullptr, nullptr, nullptr);
    cudaEventRecord(eQ, s2);

    // Fl2 -> fuse -> value -> key
    cudaStreamWaitEvent(0, eLgw, 0);
    k_gemm_mma<0><<<dim3(4, 19), 512, GEMM_SMEM>>>(
        p_h16, p_lgw, 512, 512, nullptr, p_Fl216, nullptr, nullptr, nullptr, nullptr);
    k_fuse<<<BATCH * KK, CC>>>(fuse_w, fuse_b);
    k_gemm_v<<<dim3(DD / 64, 2), 256>>>(p_Fg, v_w, p_v, BATCH * KK, DD, CC, v_b);
    cudaStreamWaitEvent(0, eKw, 0);
    k_gemm_mma<1><<<dim3(2, 19), 512, GEMM_SMEM>>>(
        p_Fl216, p_kw, 512, 256, p_k, nullptr, k_b, nullptr, nullptr, nullptr);

    cudaStreamWaitEvent(0, eQ, 0);
    k_attn<<<BATCH * PP, 256>>>();

    cudaStreamWaitEvent(0, eC1, 0);
    k_gemm_mma<2><<<dim3(4, 64), 512, GEMM_SMEM>>>(
        p_Fs16, p_c1, 256, 512, nullptr, p_Fo1b, nullptr, bn1_g, bn1_b, p_Fnhwc);

    cudaStreamWaitEvent(0, eW2, 0);
    k_conv_bulk<<<dim3(BATCH * 16, 4), 512, CONVB_SMEM>>>(
        p_Fo1b, 32, p_w2b, bn2_g, bn2_b, nullptr, p_catb);
    cudaStreamWaitEvent(0, eM1, 0);
    cudaStreamWaitEvent(0, eW3, 0);
    k_conv_bulk<<<dim3(BATCH * 16, 4), 512, CONVB_SMEM>>>(
        p_catb, 160, p_w3b, bn3_g, bn3_b, p_x3, nullptr);

    k_classifier<<<(BATCH * HW) / 64, 256>>>(drop_w, out);
}